// round 4
// baseline (speedup 1.0000x reference)
#include <cuda_runtime.h>
#include <cstdint>

// Problem dims
#define B_DIM 256
#define S_DIM 512
#define I_DIM 64
#define H_DIM 256

// Decomposition
#define CLUSTER 8          // CTAs per cluster (split H)
#define GBATCH 16          // batch rows per cluster
#define HSLICE 32          // hidden dims per CTA
#define NCOL 128           // gate columns per CTA = 4*HSLICE
#define KTOT 320           // I + H
#define K2X 32             // x k-pairs
#define K2H 128            // h k-pairs
#define NTHREADS 256       // 8 warps: 4 batch-groups x 2 k-halves

// SMEM layout (bytes)
#define OFF_B 0
#define B_BYTES (160 * NCOL * 2 * 4)        // 163840: weights [k2=160][128 cols][2]
#define OFF_AX (OFF_B + B_BYTES)
#define AX_BYTES (K2X * 16 * 2 * 4)         // 4096: x panel [32][16][2]
#define OFF_AH (OFF_AX + AX_BYTES)
#define AHBUF_BYTES (K2H * 16 * 2 * 4)      // 16384 per buffer
#define OFF_SCR (OFF_AH + 2 * AHBUF_BYTES)
#define SCR_BYTES (8 * 8 * 32 * 8)          // 16384: 8 warps x 8 accs x 32 lanes x u64
#define SMEM_BYTES (OFF_SCR + SCR_BYTES)    // 217088

__device__ __forceinline__ float sigf(float x) {
    return __fdividef(1.0f, 1.0f + __expf(-x));
}
__device__ __forceinline__ float tanh_(float x) {
    return __fdividef(2.0f, 1.0f + __expf(-2.0f * x)) - 1.0f;
}

__device__ __forceinline__ void fma2(uint64_t& d, uint64_t a, uint64_t b) {
    asm("fma.rn.f32x2 %0, %1, %2, %0;" : "+l"(d) : "l"(a), "l"(b));
}
__device__ __forceinline__ uint64_t add2(uint64_t a, uint64_t b) {
    uint64_t d;
    asm("add.rn.f32x2 %0, %1, %2;" : "=l"(d) : "l"(a), "l"(b));
    return d;
}
__device__ __forceinline__ float fold2(uint64_t v, float bias) {
    float lo, hi;
    asm("mov.b64 {%0, %1}, %2;" : "=f"(lo), "=f"(hi) : "l"(v));
    return lo + hi + bias;
}

__device__ __forceinline__ uint32_t smem_u32(const void* p) {
    uint32_t a;
    asm("{ .reg .u64 t; cvta.to.shared.u64 t, %1; cvt.u32.u64 %0, t; }"
        : "=r"(a) : "l"(p));
    return a;
}
__device__ __forceinline__ uint32_t mapa_u32(uint32_t addr, uint32_t rank) {
    uint32_t r;
    asm("mapa.shared::cluster.u32 %0, %1, %2;" : "=r"(r) : "r"(addr), "r"(rank));
    return r;
}
__device__ __forceinline__ void st_cluster_f1(uint32_t addr, float v) {
    asm volatile("st.shared::cluster.b32 [%0], %1;" :: "r"(addr), "f"(v) : "memory");
}
#define CLUSTER_BAR() do { \
    asm volatile("barrier.cluster.arrive.aligned;" ::: "memory"); \
    asm volatile("barrier.cluster.wait.aligned;" ::: "memory"); \
} while (0)

// 16 FFMA2 covering 4 batches x 4 cols x 2 k (k-pair SIMD)
#define BODY(PA, PB) do { \
    ulonglong2 _a01 = *reinterpret_cast<const ulonglong2*>(PA); \
    ulonglong2 _a23 = *reinterpret_cast<const ulonglong2*>((PA) + 4); \
    ulonglong2 _w01 = *reinterpret_cast<const ulonglong2*>(PB); \
    ulonglong2 _w23 = *reinterpret_cast<const ulonglong2*>((PB) + 4); \
    fma2(acc00, _a01.x, _w01.x); fma2(acc01, _a01.x, _w01.y); \
    fma2(acc02, _a01.x, _w23.x); fma2(acc03, _a01.x, _w23.y); \
    fma2(acc10, _a01.y, _w01.x); fma2(acc11, _a01.y, _w01.y); \
    fma2(acc12, _a01.y, _w23.x); fma2(acc13, _a01.y, _w23.y); \
    fma2(acc20, _a23.x, _w01.x); fma2(acc21, _a23.x, _w01.y); \
    fma2(acc22, _a23.x, _w23.x); fma2(acc23, _a23.x, _w23.y); \
    fma2(acc30, _a23.y, _w01.x); fma2(acc31, _a23.y, _w01.y); \
    fma2(acc32, _a23.y, _w23.x); fma2(acc33, _a23.y, _w23.y); \
} while (0)

__global__ void __cluster_dims__(CLUSTER, 1, 1) __launch_bounds__(NTHREADS, 1)
lstm_persist(const float* __restrict__ x,
             const float* __restrict__ w_i, const float* __restrict__ u_i, const float* __restrict__ b_i,
             const float* __restrict__ w_f, const float* __restrict__ u_f, const float* __restrict__ b_f,
             const float* __restrict__ w_c, const float* __restrict__ u_c, const float* __restrict__ b_c,
             const float* __restrict__ w_o, const float* __restrict__ u_o, const float* __restrict__ b_o,
             float* __restrict__ out)
{
    extern __shared__ char smem[];
    float* Bs = reinterpret_cast<float*>(smem + OFF_B);     // [160][128][2]
    float* Ax = reinterpret_cast<float*>(smem + OFF_AX);    // [32][16][2]
    float* Ah = reinterpret_cast<float*>(smem + OFF_AH);    // 2 x [128][16][2]
    uint64_t* Scr = reinterpret_cast<uint64_t*>(smem + OFF_SCR);

    const int tid  = threadIdx.x;
    const int lane = tid & 31;
    const int warp = tid >> 5;
    const int bg   = warp & 3;       // batch group
    const int kh   = warp >> 2;      // k half
    const int b0   = bg * 4;
    const int hd   = lane;

    uint32_t rank;
    asm("mov.u32 %0, %%cluster_ctarank;" : "=r"(rank));
    const int gb   = (blockIdx.x / CLUSTER) * GBATCH;
    const int colh = (int)rank * HSLICE;
    const int ghd  = colh + hd;

    // ---- stage fused weights: Bs[k>>1][4*hd+g][k&1] ----
    #pragma unroll
    for (int g = 0; g < 4; ++g) {
        const float* Wsrc = (g == 0) ? w_i : (g == 1) ? w_f : (g == 2) ? w_c : w_o;
        const float* Usrc = (g == 0) ? u_i : (g == 1) ? u_f : (g == 2) ? u_c : u_o;
        for (int k = warp; k < KTOT; k += 8) {
            const float* src = (k < I_DIM) ? (Wsrc + (size_t)k * H_DIM)
                                           : (Usrc + (size_t)(k - I_DIM) * H_DIM);
            Bs[(size_t)(k >> 1) * 256 + (size_t)(4 * lane + g) * 2 + (k & 1)] = src[colh + lane];
        }
    }
    // zero h buffer 0
    for (int i = tid; i < K2H * 32; i += NTHREADS) Ah[i] = 0.0f;

    const float bias0 = b_i[ghd], bias1 = b_f[ghd], bias2 = b_c[ghd], bias3 = b_o[ghd];

    // owned batches for this warp (gates/push/out): ob, ob+1
    const int ob = b0 + 2 * kh;

    // DSMEM push targets into peers' Ah[nxt]: h[b][ghd] -> float index ((ghd>>1)*16 + b)*2 + (ghd&1)
    const uint32_t sb = smem_u32(smem);
    const uint32_t loc = sb + OFF_AH +
        (uint32_t)((((ghd >> 1) * 16 + ob) * 2 + (ghd & 1)) * 4);
    uint32_t mb[CLUSTER];
    #pragma unroll
    for (int p = 0; p < CLUSTER; ++p) mb[p] = mapa_u32(loc, (uint32_t)p);

    // x staging: thread (bx, i0) handles 4 floats of x[gb+bx][t][i0..i0+3]
    const int bx = tid & 15;
    const int i0 = (tid >> 4) * 4;
    const float* xsrc = x + (size_t)(gb + bx) * S_DIM * I_DIM + i0;
    const int k2a = i0 >> 1;
    float2* axp0 = reinterpret_cast<float2*>(Ax + ((size_t)k2a * 16 + bx) * 2);
    float2* axp1 = reinterpret_cast<float2*>(Ax + ((size_t)(k2a + 1) * 16 + bx) * 2);

    // stage x_0
    float4 xv = *reinterpret_cast<const float4*>(xsrc);
    *axp0 = make_float2(xv.x, xv.y);
    *axp1 = make_float2(xv.z, xv.w);
    // prefetch x_1
    xv = *reinterpret_cast<const float4*>(xsrc + I_DIM);

    __syncthreads();
    CLUSTER_BAR();

    float cst0 = 0.f, cst1 = 0.f, hp0 = 0.f, hp1 = 0.f;
    int cur = 0;
    const float* Bcol = Bs + hd * 8;   // col base 4*hd -> float offset 8*hd

    uint64_t* sw = Scr + (size_t)warp * 256 + lane;            // my scratch slots
    const uint64_t* sr = Scr + (size_t)(warp ^ 4) * 256 + lane; // partner's slots

    for (int t = 0; t < S_DIM; ++t) {
        uint64_t acc00 = 0, acc01 = 0, acc02 = 0, acc03 = 0;
        uint64_t acc10 = 0, acc11 = 0, acc12 = 0, acc13 = 0;
        uint64_t acc20 = 0, acc21 = 0, acc22 = 0, acc23 = 0;
        uint64_t acc30 = 0, acc31 = 0, acc32 = 0, acc33 = 0;

        if (kh == 0) {
            // k-pairs [0,80): 32 from x, 48 from h
            const float* pa = Ax + b0 * 2;
            const float* pb = Bcol;
            #pragma unroll 4
            for (int k2 = 0; k2 < K2X; ++k2) { BODY(pa, pb); pa += 32; pb += 256; }
            pa = Ah + (size_t)cur * (K2H * 32) + b0 * 2;
            #pragma unroll 4
            for (int k2 = 0; k2 < 48; ++k2) { BODY(pa, pb); pa += 32; pb += 256; }
        } else {
            // k-pairs [80,160): h k2 48..127
            const float* pa = Ah + (size_t)cur * (K2H * 32) + 48 * 32 + b0 * 2;
            const float* pb = Bcol + 80 * 256;
            #pragma unroll 4
            for (int k2 = 0; k2 < 80; ++k2) { BODY(pa, pb); pa += 32; pb += 256; }
        }
        __syncthreads();

        // exchange partner-half partials (batches not owned by this warp)
        if (kh == 0) {
            sw[0*32] = acc20; sw[1*32] = acc21; sw[2*32] = acc22; sw[3*32] = acc23;
            sw[4*32] = acc30; sw[5*32] = acc31; sw[6*32] = acc32; sw[7*32] = acc33;
        } else {
            sw[0*32] = acc00; sw[1*32] = acc01; sw[2*32] = acc02; sw[3*32] = acc03;
            sw[4*32] = acc10; sw[5*32] = acc11; sw[6*32] = acc12; sw[7*32] = acc13;
        }
        // stage x_{t+1}
        *axp0 = make_float2(xv.x, xv.y);
        *axp1 = make_float2(xv.z, xv.w);
        __syncthreads();

        // prefetch x_{t+2} during epilogue
        if (t + 2 < S_DIM)
            xv = *reinterpret_cast<const float4*>(xsrc + (size_t)(t + 2) * I_DIM);

        // fold own accs + partner partials + bias
        float p00, p01, p02, p03, p10, p11, p12, p13;
        if (kh == 0) {
            p00 = fold2(add2(acc00, sr[0*32]), bias0);
            p01 = fold2(add2(acc01, sr[1*32]), bias1);
            p02 = fold2(add2(acc02, sr[2*32]), bias2);
            p03 = fold2(add2(acc03, sr[3*32]), bias3);
            p10 = fold2(add2(acc10, sr[4*32]), bias0);
            p11 = fold2(add2(acc11, sr[5*32]), bias1);
            p12 = fold2(add2(acc12, sr[6*32]), bias2);
            p13 = fold2(add2(acc13, sr[7*32]), bias3);
        } else {
            p00 = fold2(add2(acc20, sr[0*32]), bias0);
            p01 = fold2(add2(acc21, sr[1*32]), bias1);
            p02 = fold2(add2(acc22, sr[2*32]), bias2);
            p03 = fold2(add2(acc23, sr[3*32]), bias3);
            p10 = fold2(add2(acc30, sr[4*32]), bias0);
            p11 = fold2(add2(acc31, sr[5*32]), bias1);
            p12 = fold2(add2(acc32, sr[6*32]), bias2);
            p13 = fold2(add2(acc33, sr[7*32]), bias3);
        }

        // gates + state for 2 owned batches
        {
            float it = sigf(p00), ft = sigf(p01), gt = tanh_(p02), ot = sigf(p03);
            cst0 = fmaf(ft, cst0, it * gt);  hp0 = ot * tanh_(cst0);
        }
        {
            float it = sigf(p10), ft = sigf(p11), gt = tanh_(p12), ot = sigf(p13);
            cst1 = fmaf(ft, cst1, it * gt);  hp1 = ot * tanh_(cst1);
        }

        // hidden_seq[t][gb+ob..][ghd]
        float* op = out + (size_t)t * (B_DIM * H_DIM) + (size_t)(gb + ob) * H_DIM + ghd;
        op[0]     = hp0;
        op[H_DIM] = hp1;

        // push new h into all cluster CTAs' next buffer
        const int nxt = cur ^ 1;
        const uint32_t off = (uint32_t)nxt * AHBUF_BYTES;
        #pragma unroll
        for (int p = 0; p < CLUSTER; ++p) {
            st_cluster_f1(mb[p] + off,     hp0);
            st_cluster_f1(mb[p] + off + 8, hp1);
        }
        cur = nxt;
        CLUSTER_BAR();
    }

    // final h_t, c_t
    float* out_h = out + (size_t)S_DIM * B_DIM * H_DIM;
    float* out_c = out_h + (size_t)B_DIM * H_DIM;
    const size_t fb = (size_t)(gb + ob) * H_DIM + ghd;
    out_h[fb]         = hp0;
    out_h[fb + H_DIM] = hp1;
    out_c[fb]         = cst0;
    out_c[fb + H_DIM] = cst1;
}

extern "C" void kernel_launch(void* const* d_in, const int* in_sizes, int n_in,
                              void* d_out, int out_size) {
    const float* x   = (const float*)d_in[0];
    const float* w_i = (const float*)d_in[1];
    const float* u_i = (const float*)d_in[2];
    const float* b_i = (const float*)d_in[3];
    const float* w_f = (const float*)d_in[4];
    const float* u_f = (const float*)d_in[5];
    const float* b_f = (const float*)d_in[6];
    const float* w_c = (const float*)d_in[7];
    const float* u_c = (const float*)d_in[8];
    const float* b_c = (const float*)d_in[9];
    const float* w_o = (const float*)d_in[10];
    const float* u_o = (const float*)d_in[11];
    const float* b_o = (const float*)d_in[12];
    float* out = (float*)d_out;

    cudaFuncSetAttribute(lstm_persist,
                         cudaFuncAttributeMaxDynamicSharedMemorySize, SMEM_BYTES);

    dim3 grid((B_DIM / GBATCH) * CLUSTER);  // 16 clusters * 8 CTAs = 128
    lstm_persist<<<grid, NTHREADS, SMEM_BYTES>>>(
        x, w_i, u_i, b_i, w_f, u_f, b_f, w_c, u_c, b_c, w_o, u_o, b_o, out);
}

// round 5
// speedup vs baseline: 1.1072x; 1.1072x over previous
#include <cuda_runtime.h>
#include <cstdint>

// Problem dims
#define B_DIM 256
#define S_DIM 512
#define I_DIM 64
#define H_DIM 256

// Decomposition
#define CLUSTER 8          // CTAs per cluster (split H)
#define GBATCH 16          // batch rows per cluster
#define HSLICE 32          // hidden dims per CTA
#define NCOL 128           // gate columns per CTA = 4*HSLICE
#define KTOT 320           // I + H
#define NTHREADS 256       // 8 warps = 2 per SMSP

// SMEM layout (bytes)
#define OFF_B 0
#define B_BYTES (KTOT * NCOL * 4)           // 163840: weights [320][128], row-major
#define OFF_AX (OFF_B + B_BYTES)
#define AX_BYTES (I_DIM * 16 * 4)           // 4096: x panel [64][16]
#define OFF_AH (OFF_AX + AX_BYTES)
#define AHBUF_BYTES (H_DIM * 16 * 4)        // 16384 per buffer (x2, double buffered)
#define OFF_SCR (OFF_AH + 2 * AHBUF_BYTES)
#define SCR_BYTES (GBATCH * NCOL * 4)       // 8192: preactivation scratch [16][128]
#define SMEM_BYTES (OFF_SCR + SCR_BYTES)    // 208896

__device__ __forceinline__ float sigf(float x) {
    return __fdividef(1.0f, 1.0f + __expf(-x));
}
__device__ __forceinline__ float tanh_(float x) {
    return __fdividef(2.0f, 1.0f + __expf(-2.0f * x)) - 1.0f;
}

__device__ __forceinline__ uint64_t pk2(float lo, float hi) {
    uint64_t d;
    asm("mov.b64 %0, {%1, %2};" : "=l"(d) : "f"(lo), "f"(hi));
    return d;
}
__device__ __forceinline__ void fma2(uint64_t& d, uint64_t a, uint64_t b) {
    asm("fma.rn.f32x2 %0, %1, %2, %0;" : "+l"(d) : "l"(a), "l"(b));
}
__device__ __forceinline__ void up2(float& lo, float& hi, uint64_t v) {
    asm("mov.b64 {%0, %1}, %2;" : "=f"(lo), "=f"(hi) : "l"(v));
}

__device__ __forceinline__ uint32_t smem_u32(const void* p) {
    uint32_t a;
    asm("{ .reg .u64 t; cvta.to.shared.u64 t, %1; cvt.u32.u64 %0, t; }"
        : "=r"(a) : "l"(p));
    return a;
}
__device__ __forceinline__ uint32_t mapa_u32(uint32_t addr, uint32_t rank) {
    uint32_t r;
    asm("mapa.shared::cluster.u32 %0, %1, %2;" : "=r"(r) : "r"(addr), "r"(rank));
    return r;
}
__device__ __forceinline__ void st_cluster_f2(uint32_t addr, float a, float b) {
    asm volatile("{ .reg .b64 v; mov.b64 v, {%1, %2}; st.shared::cluster.b64 [%0], v; }"
                 :: "r"(addr), "f"(a), "f"(b) : "memory");
}
#define CLUSTER_BAR() do { \
    asm volatile("barrier.cluster.arrive.aligned;" ::: "memory"); \
    asm volatile("barrier.cluster.wait.aligned;" ::: "memory"); \
} while (0)

// Diagonal-packed inner body: 1 LDS.128 (av) + 1 LDS.64 (wv) + 4 FFMA2.
// acc_a = {q[b0][c0], q[b1][c1]}   acc_b = {q[b0][c1], q[b1][c0]}
// acc_c = {q[b2][c0], q[b3][c1]}   acc_d = {q[b2][c1], q[b3][c0]}
#define BODY(PA, PW) do { \
    float4 _a = *reinterpret_cast<const float4*>(PA); \
    float2 _w = *reinterpret_cast<const float2*>(PW); \
    uint64_t _a01 = pk2(_a.x, _a.y); \
    uint64_t _a23 = pk2(_a.z, _a.w); \
    uint64_t _w01 = pk2(_w.x, _w.y); \
    uint64_t _w10 = pk2(_w.y, _w.x); \
    fma2(acc_a, _a01, _w01); \
    fma2(acc_b, _a01, _w10); \
    fma2(acc_c, _a23, _w01); \
    fma2(acc_d, _a23, _w10); \
} while (0)

__global__ void __cluster_dims__(CLUSTER, 1, 1) __launch_bounds__(NTHREADS, 1)
lstm_persist(const float* __restrict__ x,
             const float* __restrict__ w_i, const float* __restrict__ u_i, const float* __restrict__ b_i,
             const float* __restrict__ w_f, const float* __restrict__ u_f, const float* __restrict__ b_f,
             const float* __restrict__ w_c, const float* __restrict__ u_c, const float* __restrict__ b_c,
             const float* __restrict__ w_o, const float* __restrict__ u_o, const float* __restrict__ b_o,
             float* __restrict__ out)
{
    extern __shared__ char smem[];
    float* Bs  = reinterpret_cast<float*>(smem + OFF_B);    // [320][128]
    float* Ax  = reinterpret_cast<float*>(smem + OFF_AX);   // [64][16]
    float* Ah  = reinterpret_cast<float*>(smem + OFF_AH);   // 2 x [256][16]
    float* Scr = reinterpret_cast<float*>(smem + OFF_SCR);  // [16][128]

    const int tid  = threadIdx.x;
    const int lane = tid & 31;
    const int warp = tid >> 5;

    uint32_t rank;
    asm("mov.u32 %0, %%cluster_ctarank;" : "=r"(rank));
    const int gb   = (blockIdx.x / CLUSTER) * GBATCH;
    const int colh = (int)rank * HSLICE;

    // ---- stage fused weights (row-major, gate-interleaved cols): Bs[k][4*hd+g] ----
    #pragma unroll
    for (int g = 0; g < 4; ++g) {
        const float* Wsrc = (g == 0) ? w_i : (g == 1) ? w_f : (g == 2) ? w_c : w_o;
        const float* Usrc = (g == 0) ? u_i : (g == 1) ? u_f : (g == 2) ? u_c : u_o;
        for (int k = warp; k < KTOT; k += 8) {
            const float* src = (k < I_DIM) ? (Wsrc + (size_t)k * H_DIM)
                                           : (Usrc + (size_t)(k - I_DIM) * H_DIM);
            Bs[k * NCOL + 4 * lane + g] = src[colh + lane];
        }
    }
    // zero h buffer 0
    for (int i = tid; i < H_DIM * 16; i += NTHREADS) Ah[i] = 0.0f;

    // ---- matmul thread coords: warp = (col slice, batch half); lane = 2 cols x 4 batches
    const int cb = (warp & 3) * 32 + 2 * (lane & 15);   // cols cb, cb+1
    const int bb = (warp >> 2) * 8 + 4 * (lane >> 4);   // batches bb..bb+3

    // ---- epilogue coords: thread owns hidden dim (lane) for batches 2*warp, 2*warp+1
    const int eb  = warp * 2;
    const int ghd = colh + lane;
    const float bias0 = b_i[ghd], bias1 = b_f[ghd], bias2 = b_c[ghd], bias3 = b_o[ghd];

    // DSMEM push targets: Ah[nxt][ghd][eb..eb+1] in every cluster CTA (b64)
    const uint32_t sb  = smem_u32(smem);
    const uint32_t loc = sb + OFF_AH + (uint32_t)((ghd * 16 + eb) * 4);
    uint32_t mb[CLUSTER];
    #pragma unroll
    for (int p = 0; p < CLUSTER; ++p) mb[p] = mapa_u32(loc, (uint32_t)p);

    // x staging: thread (bx, i0) handles 4 floats of x[gb+bx][t][i0..i0+3]
    const int bx = tid & 15;
    const int i0 = (tid >> 4) * 4;
    const float* xsrc = x + (size_t)(gb + bx) * S_DIM * I_DIM + i0;

    float4 xv = *reinterpret_cast<const float4*>(xsrc);          // x_0
    float4 xn = *reinterpret_cast<const float4*>(xsrc + I_DIM);  // x_1 prefetch

    float cs0 = 0.f, cs1 = 0.f, h0 = 0.f, h1 = 0.f;
    int cur = 0;

    const float* pW  = Bs + cb;             // weight col pair base
    const float* pAx = Ax + bb;

    __syncthreads();
    CLUSTER_BAR();

    for (int t = 0; t < S_DIM; ++t) {
        // stage x_t
        Ax[(i0 + 0) * 16 + bx] = xv.x;
        Ax[(i0 + 1) * 16 + bx] = xv.y;
        Ax[(i0 + 2) * 16 + bx] = xv.z;
        Ax[(i0 + 3) * 16 + bx] = xv.w;
        __syncthreads();

        uint64_t acc_a = 0, acc_b = 0, acc_c = 0, acc_d = 0;

        // x part: k in [0,64)
        #pragma unroll 8
        for (int k = 0; k < I_DIM; ++k)
            BODY(pAx + k * 16, pW + k * NCOL);

        // prefetch x_{t+2} while the h-part runs
        xv = xn;
        if (t + 2 < S_DIM)
            xn = *reinterpret_cast<const float4*>(xsrc + (size_t)(t + 2) * I_DIM);

        // h part: k in [64,320)
        {
            const float* pAh = Ah + (size_t)cur * (H_DIM * 16) + bb;
            const float* pWh = pW + I_DIM * NCOL;
            #pragma unroll 8
            for (int k = 0; k < H_DIM; ++k)
                BODY(pAh + k * 16, pWh + k * NCOL);
        }

        // un-scramble diagonal packing into scratch [b][col]
        {
            float lo, hi;
            up2(lo, hi, acc_a); Scr[(bb + 0) * NCOL + cb]     = lo; Scr[(bb + 1) * NCOL + cb + 1] = hi;
            up2(lo, hi, acc_b); Scr[(bb + 0) * NCOL + cb + 1] = lo; Scr[(bb + 1) * NCOL + cb]     = hi;
            up2(lo, hi, acc_c); Scr[(bb + 2) * NCOL + cb]     = lo; Scr[(bb + 3) * NCOL + cb + 1] = hi;
            up2(lo, hi, acc_d); Scr[(bb + 2) * NCOL + cb + 1] = lo; Scr[(bb + 3) * NCOL + cb]     = hi;
        }
        __syncthreads();

        // gates + state for 2 owned batches (this thread: hidden dim `lane`)
        {
            float4 q = *reinterpret_cast<const float4*>(Scr + eb * NCOL + 4 * lane);
            float it = sigf(q.x + bias0), ft = sigf(q.y + bias1);
            float gt = tanh_(q.z + bias2), ot = sigf(q.w + bias3);
            cs0 = fmaf(ft, cs0, it * gt);
            h0  = ot * tanh_(cs0);
        }
        {
            float4 q = *reinterpret_cast<const float4*>(Scr + (eb + 1) * NCOL + 4 * lane);
            float it = sigf(q.x + bias0), ft = sigf(q.y + bias1);
            float gt = tanh_(q.z + bias2), ot = sigf(q.w + bias3);
            cs1 = fmaf(ft, cs1, it * gt);
            h1  = ot * tanh_(cs1);
        }

        // hidden_seq[t][gb+eb..][ghd]  (coalesced: lanes span 128B per batch row)
        float* op = out + (size_t)t * (B_DIM * H_DIM) + (size_t)(gb + eb) * H_DIM + ghd;
        op[0]     = h0;
        op[H_DIM] = h1;

        // push new h pair into all cluster CTAs' next buffer
        const int nxt = cur ^ 1;
        const uint32_t off = (uint32_t)nxt * AHBUF_BYTES;
        #pragma unroll
        for (int p = 0; p < CLUSTER; ++p)
            st_cluster_f2(mb[p] + off, h0, h1);
        cur = nxt;
        CLUSTER_BAR();   // release pushes; acquire peers' pushes
    }

    // final h_t, c_t
    float* out_h = out + (size_t)S_DIM * B_DIM * H_DIM;
    float* out_c = out_h + (size_t)B_DIM * H_DIM;
    const size_t fb = (size_t)(gb + eb) * H_DIM + ghd;
    out_h[fb]         = h0;
    out_h[fb + H_DIM] = h1;
    out_c[fb]         = cs0;
    out_c[fb + H_DIM] = cs1;
}

extern "C" void kernel_launch(void* const* d_in, const int* in_sizes, int n_in,
                              void* d_out, int out_size) {
    const float* x   = (const float*)d_in[0];
    const float* w_i = (const float*)d_in[1];
    const float* u_i = (const float*)d_in[2];
    const float* b_i = (const float*)d_in[3];
    const float* w_f = (const float*)d_in[4];
    const float* u_f = (const float*)d_in[5];
    const float* b_f = (const float*)d_in[6];
    const float* w_c = (const float*)d_in[7];
    const float* u_c = (const float*)d_in[8];
    const float* b_c = (const float*)d_in[9];
    const float* w_o = (const float*)d_in[10];
    const float* u_o = (const float*)d_in[11];
    const float* b_o = (const float*)d_in[12];
    float* out = (float*)d_out;

    cudaFuncSetAttribute(lstm_persist,
                         cudaFuncAttributeMaxDynamicSharedMemorySize, SMEM_BYTES);

    dim3 grid((B_DIM / GBATCH) * CLUSTER);  // 16 clusters * 8 CTAs = 128
    lstm_persist<<<grid, NTHREADS, SMEM_BYTES>>>(
        x, w_i, u_i, b_i, w_f, u_f, b_f, w_c, u_c, b_c, w_o, u_o, b_o, out);
}

// round 7
// speedup vs baseline: 1.3105x; 1.1837x over previous
#include <cuda_runtime.h>
#include <cuda_bf16.h>
#include <cstdint>

// Problem dims
#define B_DIM 256
#define S_DIM 512
#define I_DIM 64
#define H_DIM 256

#define CLUSTER 8
#define GBATCH 16
#define HSLICE 32
#define NTHREADS 256      // 8 warps

// Weights: [2 half][320 k][128 n] bf16, pitch 272B (conflict-free LDSM)
#define WPITCH 272
#define OFF_W   0
#define WHALF   (320 * WPITCH)            // 87040
// A x-panel: [2 buf][2 half][64 k][16 b] bf16
#define OFF_AX  (2 * WHALF)               // 174080
#define AXBUF   4096
// A h-panel: [2 buf][2 half][256 k][16 b] bf16
#define OFF_AH  (OFF_AX + 2 * AXBUF)      // 182272
#define AHBUF   16384
// scratch: [16 b][128 col] fp32
#define OFF_SCR (OFF_AH + 2 * AHBUF)      // 215040
#define SMEM_BYTES (OFF_SCR + 8192)       // 223232

__device__ __forceinline__ float sigf(float x) {
    return __fdividef(1.0f, 1.0f + __expf(-x));
}
__device__ __forceinline__ float tanh_(float x) {
    return __fdividef(2.0f, 1.0f + __expf(-2.0f * x)) - 1.0f;
}

__device__ __forceinline__ uint32_t smem_u32(const void* p) {
    uint32_t a;
    asm("{ .reg .u64 t; cvta.to.shared.u64 t, %1; cvt.u32.u64 %0, t; }" : "=r"(a) : "l"(p));
    return a;
}
__device__ __forceinline__ uint32_t mapa_u32(uint32_t addr, uint32_t rank) {
    uint32_t r;
    asm("mapa.shared::cluster.u32 %0, %1, %2;" : "=r"(r) : "r"(addr), "r"(rank));
    return r;
}
__device__ __forceinline__ void stc32(uint32_t addr, uint32_t v) {
    asm volatile("st.shared::cluster.u32 [%0], %1;" :: "r"(addr), "r"(v) : "memory");
}
#define CLUSTER_BAR() do { \
    asm volatile("barrier.cluster.arrive.aligned;" ::: "memory"); \
    asm volatile("barrier.cluster.wait.aligned;" ::: "memory"); \
} while (0)

#define LDSM4T(r0, r1, r2, r3, addr) \
    asm volatile("ldmatrix.sync.aligned.m8n8.x4.trans.shared.b16 {%0,%1,%2,%3}, [%4];" \
                 : "=r"(r0), "=r"(r1), "=r"(r2), "=r"(r3) : "r"(addr))

#define MMA(d0, d1, d2, d3, a0, a1, a2, a3, b0, b1) \
    asm volatile("mma.sync.aligned.m16n8k16.row.col.f32.bf16.bf16.f32 " \
                 "{%0,%1,%2,%3}, {%4,%5,%6,%7}, {%8,%9}, {%0,%1,%2,%3};" \
                 : "+f"(d0), "+f"(d1), "+f"(d2), "+f"(d3) \
                 : "r"(a0), "r"(a1), "r"(a2), "r"(a3), "r"(b0), "r"(b1))

__device__ __forceinline__ void bfsplit(float v, uint16_t& hi, uint16_t& lo) {
    __nv_bfloat16 h = __float2bfloat16(v);
    float r = v - __bfloat162float(h);
    __nv_bfloat16 l = __float2bfloat16(r);
    hi = *reinterpret_cast<uint16_t*>(&h);
    lo = *reinterpret_cast<uint16_t*>(&l);
}

__global__ void __cluster_dims__(CLUSTER, 1, 1) __launch_bounds__(NTHREADS, 1)
lstm_hmma(const float* __restrict__ x,
          const float* __restrict__ w_i, const float* __restrict__ u_i, const float* __restrict__ b_i,
          const float* __restrict__ w_f, const float* __restrict__ u_f, const float* __restrict__ b_f,
          const float* __restrict__ w_c, const float* __restrict__ u_c, const float* __restrict__ b_c,
          const float* __restrict__ w_o, const float* __restrict__ u_o, const float* __restrict__ b_o,
          float* __restrict__ out)
{
    extern __shared__ char smem[];
    const uint32_t sb = smem_u32(smem);
    const int tid  = threadIdx.x;
    const int lane = tid & 31;
    const int warp = tid >> 5;

    uint32_t rank;
    asm("mov.u32 %0, %%cluster_ctarank;" : "=r"(rank));
    const int gb   = (blockIdx.x / CLUSTER) * GBATCH;
    const int colh = (int)rank * HSLICE;

    // ---- stage weights: W[half][k][n], n = 4*hd + g, bf16 hi/lo ----
    #pragma unroll
    for (int g = 0; g < 4; ++g) {
        const float* Wsrc = (g == 0) ? w_i : (g == 1) ? w_f : (g == 2) ? w_c : w_o;
        const float* Usrc = (g == 0) ? u_i : (g == 1) ? u_f : (g == 2) ? u_c : u_o;
        for (int k = warp; k < 320; k += 8) {
            const float* src = (k < I_DIM) ? (Wsrc + (size_t)k * H_DIM)
                                           : (Usrc + (size_t)(k - I_DIM) * H_DIM);
            float v = src[colh + lane];
            uint16_t hi, lo;
            bfsplit(v, hi, lo);
            uint32_t o = (uint32_t)k * WPITCH + (uint32_t)(4 * lane + g) * 2;
            *reinterpret_cast<uint16_t*>(smem + OFF_W + o)         = hi;
            *reinterpret_cast<uint16_t*>(smem + OFF_W + WHALF + o) = lo;
        }
    }
    // zero h panel buffer 0 (both halves)
    for (int i = tid; i < AHBUF / 4; i += NTHREADS)
        reinterpret_cast<uint32_t*>(smem + OFF_AH)[i] = 0;

    // ---- lane offsets for ldmatrix.x4.trans ----
    const int lg = lane >> 3, lr = lane & 7;
    // A (from [k][16b]): m0=(k0-7,b0-7) m1=(k0-7,b8-15) m2=(k8-15,b0-7) m3=(k8-15,b8-15)
    const uint32_t aoff = (uint32_t)((((lg & 2) ? 8 : 0) + lr) * 32 + ((lg & 1) ? 16 : 0));
    // B (from [k][128n]): m0=(k0-7,n0-7) m1=(k8-15,n0-7) m2=(k0-7,n8-15) m3=(k8-15,n8-15)
    const uint32_t boff = (uint32_t)((((lg & 1) ? 8 : 0) + lr) * WPITCH
                                     + (16 * warp + ((lg & 2) ? 8 : 0)) * 2);

    // ---- bias-initialized accumulator constants (per ntile, col pair) ----
    float biasA[2], biasB[2];
    #pragma unroll
    for (int j = 0; j < 2; ++j) {
        int c0 = 16 * warp + 8 * j + 2 * (lane & 3);
        int hd0 = c0 >> 2, g0 = c0 & 3;
        const float* p0 = (g0 == 0) ? b_i : (g0 == 2) ? b_c : (g0 == 1) ? b_f : b_o;
        const float* p1 = (g0 + 1 == 1) ? b_f : (g0 + 1 == 3) ? b_o : (g0 + 1 == 2) ? b_c : b_i;
        biasA[j] = p0[colh + hd0];
        biasB[j] = p1[colh + hd0];
    }

    // ---- epilogue constants: thread owns hd=lane, batches eb, eb+1 ----
    const int eb  = 2 * warp;
    const int ghd = colh + lane;
    const float bi0 = b_i[ghd], bf0 = b_f[ghd], bc0 = b_c[ghd], bo0 = b_o[ghd];
    (void)bi0; (void)bf0; (void)bc0; (void)bo0; // biases already in accs

    const uint32_t pof = (uint32_t)(ghd * 32 + eb * 2);  // offset within one AH half
    uint32_t mbAH[CLUSTER];
    #pragma unroll
    for (int p = 0; p < CLUSTER; ++p) mbAH[p] = mapa_u32(sb + OFF_AH, (uint32_t)p);

    // ---- x staging: thread (bx, kg) handles x[gb+bx][t][4kg..4kg+3] ----
    const int bx = tid & 15;
    const int kg = tid >> 4;
    const float* xsrc = x + (size_t)(gb + bx) * S_DIM * I_DIM + 4 * kg;

    // stage x_0 into buf 0
    {
        float4 v = *reinterpret_cast<const float4*>(xsrc);
        float vv[4] = {v.x, v.y, v.z, v.w};
        #pragma unroll
        for (int j = 0; j < 4; ++j) {
            uint16_t hi, lo;
            bfsplit(vv[j], hi, lo);
            uint32_t o = (uint32_t)(4 * kg + j) * 32 + (uint32_t)bx * 2;
            *reinterpret_cast<uint16_t*>(smem + OFF_AX + o)        = hi;
            *reinterpret_cast<uint16_t*>(smem + OFF_AX + 2048 + o) = lo;
        }
    }
    float4 xv = *reinterpret_cast<const float4*>(xsrc + I_DIM);  // x_1 prefetch

    float* Scr = reinterpret_cast<float*>(smem + OFF_SCR);
    float cs0 = 0.f, cs1 = 0.f, h0 = 0.f, h1 = 0.f;

    __syncthreads();
    CLUSTER_BAR();

    for (int t = 0; t < S_DIM; ++t) {
        const int cur = t & 1;
        const int nxt = cur ^ 1;

        float d00 = biasA[0], d01 = biasB[0], d02 = biasA[0], d03 = biasB[0];
        float d10 = biasA[1], d11 = biasB[1], d12 = biasA[1], d13 = biasB[1];

        const uint32_t axb = sb + OFF_AX + (uint32_t)cur * AXBUF + aoff;
        const uint32_t ahb = sb + OFF_AH + (uint32_t)cur * AHBUF + aoff;
        const uint32_t wbb = sb + OFF_W + boff;

        #pragma unroll
        for (int ks = 0; ks < 20; ++ks) {
            uint32_t aHi = (ks < 4) ? (axb + (uint32_t)ks * 512)
                                    : (ahb + (uint32_t)(ks - 4) * 512);
            uint32_t aLo = aHi + ((ks < 4) ? 2048u : 8192u);
            uint32_t wHi = wbb + (uint32_t)ks * (16 * WPITCH);
            uint32_t wLo = wHi + WHALF;

            uint32_t ah0, ah1, ah2, ah3, al0, al1, al2, al3;
            uint32_t bh0, bh1, bh2, bh3, bl0, bl1, bl2, bl3;
            LDSM4T(ah0, ah1, ah2, ah3, aHi);
            LDSM4T(al0, al1, al2, al3, aLo);
            LDSM4T(bh0, bh1, bh2, bh3, wHi);
            LDSM4T(bl0, bl1, bl2, bl3, wLo);

            // ntile 0
            MMA(d00, d01, d02, d03, ah0, ah1, ah2, ah3, bh0, bh1);
            MMA(d00, d01, d02, d03, ah0, ah1, ah2, ah3, bl0, bl1);
            MMA(d00, d01, d02, d03, al0, al1, al2, al3, bh0, bh1);
            // ntile 1
            MMA(d10, d11, d12, d13, ah0, ah1, ah2, ah3, bh2, bh3);
            MMA(d10, d11, d12, d13, ah0, ah1, ah2, ah3, bl2, bl3);
            MMA(d10, d11, d12, d13, al0, al1, al2, al3, bh2, bh3);
        }

        // ---- stage x_{t+1} into buf nxt; prefetch x_{t+2} ----
        if (t + 1 < S_DIM) {
            const uint32_t xb = sb; (void)xb;
            const uint32_t xo = OFF_AX + (uint32_t)nxt * AXBUF;
            float vv[4] = {xv.x, xv.y, xv.z, xv.w};
            #pragma unroll
            for (int j = 0; j < 4; ++j) {
                uint16_t hi, lo;
                bfsplit(vv[j], hi, lo);
                uint32_t o = (uint32_t)(4 * kg + j) * 32 + (uint32_t)bx * 2;
                *reinterpret_cast<uint16_t*>(smem + xo + o)        = hi;
                *reinterpret_cast<uint16_t*>(smem + xo + 2048 + o) = lo;
            }
            if (t + 2 < S_DIM)
                xv = *reinterpret_cast<const float4*>(xsrc + (size_t)(t + 2) * I_DIM);
        }

        // ---- scatter D to scratch [b][128] ----
        {
            const int r  = lane >> 2;
            const int c0 = 2 * (lane & 3);
            #pragma unroll
            for (int j = 0; j < 2; ++j) {
                const int col = 16 * warp + 8 * j + c0;
                float2* s0 = reinterpret_cast<float2*>(Scr + r * 128 + col);
                float2* s1 = reinterpret_cast<float2*>(Scr + (r + 8) * 128 + col);
                *s0 = make_float2(j ? d10 : d00, j ? d11 : d01);
                *s1 = make_float2(j ? d12 : d02, j ? d13 : d03);
            }
        }
        __syncthreads();

        // ---- gates for (hd=lane, batches eb, eb+1); bias already in accs ----
        uint16_t h0hi, h0lo, h1hi, h1lo;
        {
            float4 q = *reinterpret_cast<const float4*>(Scr + eb * 128 + 4 * lane);
            float it = sigf(q.x), ft = sigf(q.y), gt = tanh_(q.z), ot = sigf(q.w);
            cs0 = fmaf(ft, cs0, it * gt);
            h0  = ot * tanh_(cs0);
            bfsplit(h0, h0hi, h0lo);
        }
        {
            float4 q = *reinterpret_cast<const float4*>(Scr + (eb + 1) * 128 + 4 * lane);
            float it = sigf(q.x), ft = sigf(q.y), gt = tanh_(q.z), ot = sigf(q.w);
            cs1 = fmaf(ft, cs1, it * gt);
            h1  = ot * tanh_(cs1);
            bfsplit(h1, h1hi, h1lo);
        }

        // hidden_seq[t][gb+eb..][ghd]
        float* op = out + (size_t)t * (B_DIM * H_DIM) + (size_t)(gb + eb) * H_DIM + ghd;
        op[0]     = h0;
        op[H_DIM] = h1;

        // ---- push h (bf16 hi/lo, 2 batches packed) into all peers' AH[nxt] ----
        const uint32_t hiw = (uint32_t)h0hi | ((uint32_t)h1hi << 16);
        const uint32_t low = (uint32_t)h0lo | ((uint32_t)h1lo << 16);
        const uint32_t bo  = (uint32_t)nxt * AHBUF;
        #pragma unroll
        for (int p = 0; p < CLUSTER; ++p) {
            stc32(mbAH[p] + bo + pof,        hiw);
            stc32(mbAH[p] + bo + 8192 + pof, low);
        }

        CLUSTER_BAR();   // pushes + x staging visible for step t+1
    }

    // ---- final h_t, c_t ----
    float* out_h = out + (size_t)S_DIM * B_DIM * H_DIM;
    float* out_c = out_h + (size_t)B_DIM * H_DIM;
    const size_t fb = (size_t)(gb + eb) * H_DIM + ghd;
    out_h[fb]         = h0;
    out_h[fb + H_DIM] = h1;
    out_c[fb]         = cs0;
    out_c[fb + H_DIM] = cs1;
}

extern "C" void kernel_launch(void* const* d_in, const int* in_sizes, int n_in,
                              void* d_out, int out_size) {
    const float* x   = (const float*)d_in[0];
    const float* w_i = (const float*)d_in[1];
    const float* u_i = (const float*)d_in[2];
    const float* b_i = (const float*)d_in[3];
    const float* w_f = (const float*)d_in[4];
    const float* u_f = (const float*)d_in[5];
    const float* b_f = (const float*)d_in[6];
    const float* w_c = (const float*)d_in[7];
    const float* u_c = (const float*)d_in[8];
    const float* b_c = (const float*)d_in[9];
    const float* w_o = (const float*)d_in[10];
    const float* u_o = (const float*)d_in[11];
    const float* b_o = (const float*)d_in[12];
    float* out = (float*)d_out;

    cudaFuncSetAttribute(lstm_hmma, cudaFuncAttributeMaxDynamicSharedMemorySize, SMEM_BYTES);

    dim3 grid((B_DIM / GBATCH) * CLUSTER);  // 16 clusters * 8 CTAs = 128
    lstm_hmma<<<grid, NTHREADS, SMEM_BYTES>>>(
        x, w_i, u_i, b_i, w_f, u_f, b_f, w_c, u_c, b_c, w_o, u_o, b_o, out);
}

// round 9
// speedup vs baseline: 2.4749x; 1.8885x over previous
#include <cuda_runtime.h>
#include <cuda_bf16.h>
#include <cstdint>

// Problem dims
#define B_DIM 256
#define S_DIM 512
#define I_DIM 64
#define H_DIM 256

#define CLUSTER 8
#define GBATCH 16
#define HSLICE 32
#define NTHREADS 256      // 8 warps

// Weights: [2 half][320 k][128 n] bf16, pitch 272B (conflict-free LDSM)
#define WPITCH 272
#define OFF_W   0
#define WHALF   (320 * WPITCH)            // 87040
// A x-panel: [2 buf][2 half][64 k][16 b] bf16
#define OFF_AX  (2 * WHALF)               // 174080
#define AXBUF   4096
// A h-panel: [2 buf][2 half][256 k][16 b] bf16
#define OFF_AH  (OFF_AX + 2 * AXBUF)      // 182272
#define AHBUF   16384
// scratch: [16 b][128 col] fp32
#define OFF_SCR (OFF_AH + 2 * AHBUF)      // 215040
// h staging for compact pushes: [32 hd][2 half][16 b] bf16 = 2KB
#define OFF_HSTG (OFF_SCR + 8192)         // 223232
#define SMEM_BYTES (OFF_HSTG + 2048)      // 225280

__device__ __forceinline__ float sigf(float x) {
    return __fdividef(1.0f, 1.0f + __expf(-x));
}
__device__ __forceinline__ float tanh_(float x) {
    return __fdividef(2.0f, 1.0f + __expf(-2.0f * x)) - 1.0f;
}

__device__ __forceinline__ uint32_t smem_u32(const void* p) {
    uint32_t a;
    asm("{ .reg .u64 t; cvta.to.shared.u64 t, %1; cvt.u32.u64 %0, t; }" : "=r"(a) : "l"(p));
    return a;
}
__device__ __forceinline__ uint32_t mapa_u32(uint32_t addr, uint32_t rank) {
    uint32_t r;
    asm("mapa.shared::cluster.u32 %0, %1, %2;" : "=r"(r) : "r"(addr), "r"(rank));
    return r;
}
__device__ __forceinline__ void stc128(uint32_t addr, uint4 v) {
    asm volatile("st.shared::cluster.v4.b32 [%0], {%1,%2,%3,%4};"
                 :: "r"(addr), "r"(v.x), "r"(v.y), "r"(v.z), "r"(v.w) : "memory");
}
#define CLUSTER_ARRIVE() asm volatile("barrier.cluster.arrive.aligned;" ::: "memory")
#define CLUSTER_WAIT()   asm volatile("barrier.cluster.wait.aligned;" ::: "memory")

#define LDSM4T(r0, r1, r2, r3, addr) \
    asm volatile("ldmatrix.sync.aligned.m8n8.x4.trans.shared.b16 {%0,%1,%2,%3}, [%4];" \
                 : "=r"(r0), "=r"(r1), "=r"(r2), "=r"(r3) : "r"(addr))

#define MMA(d0, d1, d2, d3, a0, a1, a2, a3, b0, b1) \
    asm volatile("mma.sync.aligned.m16n8k16.row.col.f32.bf16.bf16.f32 " \
                 "{%0,%1,%2,%3}, {%4,%5,%6,%7}, {%8,%9}, {%0,%1,%2,%3};" \
                 : "+f"(d0), "+f"(d1), "+f"(d2), "+f"(d3) \
                 : "r"(a0), "r"(a1), "r"(a2), "r"(a3), "r"(b0), "r"(b1))

__device__ __forceinline__ void bfsplit(float v, uint16_t& hi, uint16_t& lo) {
    __nv_bfloat16 h = __float2bfloat16(v);
    float r = v - __bfloat162float(h);
    __nv_bfloat16 l = __float2bfloat16(r);
    hi = *reinterpret_cast<uint16_t*>(&h);
    lo = *reinterpret_cast<uint16_t*>(&l);
}

// 6 MMAs (3-term bf16 split, 2 n-tiles) on one k-step's fragments
#define MMA6(AH, AL, BH, BL) do { \
    MMA(d00, d01, d02, d03, (AH)[0], (AH)[1], (AH)[2], (AH)[3], (BH)[0], (BH)[1]); \
    MMA(d00, d01, d02, d03, (AH)[0], (AH)[1], (AH)[2], (AH)[3], (BL)[0], (BL)[1]); \
    MMA(d00, d01, d02, d03, (AL)[0], (AL)[1], (AL)[2], (AL)[3], (BH)[0], (BH)[1]); \
    MMA(d10, d11, d12, d13, (AH)[0], (AH)[1], (AH)[2], (AH)[3], (BH)[2], (BH)[3]); \
    MMA(d10, d11, d12, d13, (AH)[0], (AH)[1], (AH)[2], (AH)[3], (BL)[2], (BL)[3]); \
    MMA(d10, d11, d12, d13, (AL)[0], (AL)[1], (AL)[2], (AL)[3], (BH)[2], (BH)[3]); \
} while (0)

// ALOFF: byte distance between hi and lo halves of the A panel
// (x panel: 2048, h panel: 8192) — R8's bug was hard-coding 8192.
#define LOADKS(S, AADDR, ALOFF, WADDR) do { \
    LDSM4T(fah[S][0], fah[S][1], fah[S][2], fah[S][3], (AADDR)); \
    LDSM4T(fal[S][0], fal[S][1], fal[S][2], fal[S][3], (AADDR) + (ALOFF)); \
    LDSM4T(fbh[S][0], fbh[S][1], fbh[S][2], fbh[S][3], (WADDR)); \
    LDSM4T(fbl[S][0], fbl[S][1], fbl[S][2], fbl[S][3], (WADDR) + WHALF); \
} while (0)

__global__ void __cluster_dims__(CLUSTER, 1, 1) __launch_bounds__(NTHREADS, 1)
lstm_hmma(const float* __restrict__ x,
          const float* __restrict__ w_i, const float* __restrict__ u_i, const float* __restrict__ b_i,
          const float* __restrict__ w_f, const float* __restrict__ u_f, const float* __restrict__ b_f,
          const float* __restrict__ w_c, const float* __restrict__ u_c, const float* __restrict__ b_c,
          const float* __restrict__ w_o, const float* __restrict__ u_o, const float* __restrict__ b_o,
          float* __restrict__ out)
{
    extern __shared__ char smem[];
    const uint32_t sb = smem_u32(smem);
    const int tid  = threadIdx.x;
    const int lane = tid & 31;
    const int warp = tid >> 5;

    uint32_t rank;
    asm("mov.u32 %0, %%cluster_ctarank;" : "=r"(rank));
    const int gb   = (blockIdx.x / CLUSTER) * GBATCH;
    const int colh = (int)rank * HSLICE;

    // ---- stage weights: W[half][k][n], n = 4*hd + g, bf16 hi/lo ----
    #pragma unroll
    for (int g = 0; g < 4; ++g) {
        const float* Wsrc = (g == 0) ? w_i : (g == 1) ? w_f : (g == 2) ? w_c : w_o;
        const float* Usrc = (g == 0) ? u_i : (g == 1) ? u_f : (g == 2) ? u_c : u_o;
        for (int k = warp; k < 320; k += 8) {
            const float* src = (k < I_DIM) ? (Wsrc + (size_t)k * H_DIM)
                                           : (Usrc + (size_t)(k - I_DIM) * H_DIM);
            float v = src[colh + lane];
            uint16_t hi, lo;
            bfsplit(v, hi, lo);
            uint32_t o = (uint32_t)k * WPITCH + (uint32_t)(4 * lane + g) * 2;
            *reinterpret_cast<uint16_t*>(smem + OFF_W + o)         = hi;
            *reinterpret_cast<uint16_t*>(smem + OFF_W + WHALF + o) = lo;
        }
    }
    // zero h panel buffer 0 (both halves)
    for (int i = tid; i < AHBUF / 4; i += NTHREADS)
        reinterpret_cast<uint32_t*>(smem + OFF_AH)[i] = 0;

    // ---- lane offsets for ldmatrix.x4.trans ----
    const int lg = lane >> 3, lr = lane & 7;
    const uint32_t aoff = (uint32_t)((((lg & 2) ? 8 : 0) + lr) * 32 + ((lg & 1) ? 16 : 0));
    const uint32_t boff = (uint32_t)((((lg & 1) ? 8 : 0) + lr) * WPITCH
                                     + (16 * warp + ((lg & 2) ? 8 : 0)) * 2);

    // ---- bias-initialized accumulator constants ----
    float biasA[2], biasB[2];
    #pragma unroll
    for (int j = 0; j < 2; ++j) {
        int c0 = 16 * warp + 8 * j + 2 * (lane & 3);
        int hd0 = c0 >> 2, g0 = c0 & 3;
        const float* p0 = (g0 == 0) ? b_i : (g0 == 2) ? b_c : (g0 == 1) ? b_f : b_o;
        const float* p1 = (g0 + 1 == 1) ? b_f : (g0 + 1 == 3) ? b_o : (g0 + 1 == 2) ? b_c : b_i;
        biasA[j] = p0[colh + hd0];
        biasB[j] = p1[colh + hd0];
    }

    // ---- epilogue constants: thread owns hd=lane, batches eb, eb+1 ----
    const int eb  = 2 * warp;
    const int ghd = colh + lane;

    // ---- pusher constants (tid < 128): 16-B chunk (hd, half, bgroup) ----
    const int phd   = tid & 31;
    const int phalf = (tid >> 5) & 1;
    const int pbg   = (tid >> 6) & 1;
    const uint32_t psrc  = (uint32_t)(phd * 64 + phalf * 32 + pbg * 16);
    const uint32_t pdoff = (uint32_t)(phalf * 8192 + (colh + phd) * 32 + pbg * 16);
    uint32_t mbAH[CLUSTER];
    #pragma unroll
    for (int p = 0; p < CLUSTER; ++p) mbAH[p] = mapa_u32(sb + OFF_AH, (uint32_t)p);

    // ---- x staging: thread (bx, kg) handles x[gb+bx][t][4kg..4kg+3] ----
    const int bx = tid & 15;
    const int kg = tid >> 4;
    const float* xsrc = x + (size_t)(gb + bx) * S_DIM * I_DIM + 4 * kg;

    {
        float4 v = *reinterpret_cast<const float4*>(xsrc);
        float vv[4] = {v.x, v.y, v.z, v.w};
        #pragma unroll
        for (int j = 0; j < 4; ++j) {
            uint16_t hi, lo;
            bfsplit(vv[j], hi, lo);
            uint32_t o = (uint32_t)(4 * kg + j) * 32 + (uint32_t)bx * 2;
            *reinterpret_cast<uint16_t*>(smem + OFF_AX + o)        = hi;
            *reinterpret_cast<uint16_t*>(smem + OFF_AX + 2048 + o) = lo;
        }
    }
    float4 xv = *reinterpret_cast<const float4*>(xsrc + I_DIM);  // x_1 prefetch

    float* Scr = reinterpret_cast<float*>(smem + OFF_SCR);
    float cs0 = 0.f, cs1 = 0.f, h0 = 0.f, h1 = 0.f;

    __syncthreads();
    CLUSTER_ARRIVE();   // primes iteration-0 wait (h buffer 0 locally zeroed)

    for (int t = 0; t < S_DIM; ++t) {
        const int cur = t & 1;
        const int nxt = cur ^ 1;

        float d00 = biasA[0], d01 = biasB[0], d02 = biasA[0], d03 = biasB[0];
        float d10 = biasA[1], d11 = biasB[1], d12 = biasA[1], d13 = biasB[1];

        const uint32_t axb = sb + OFF_AX + (uint32_t)cur * AXBUF + aoff;
        const uint32_t ahb = sb + OFF_AH + (uint32_t)cur * AHBUF + aoff;
        const uint32_t wxb = sb + OFF_W + boff;
        const uint32_t whb = wxb + 4u * (16 * WPITCH);

        uint32_t fah[2][4], fal[2][4], fbh[2][4], fbl[2][4];

        // ===== phase 1: x-part (4 ks) — independent of peers' h, overlaps barrier =====
        LOADKS(0, axb, 2048u, wxb);
        #pragma unroll
        for (int ks = 0; ks < 4; ++ks) {
            const int s = ks & 1, n = s ^ 1;
            if (ks + 1 < 4)
                LOADKS(n, axb + (uint32_t)(ks + 1) * 512, 2048u,
                       wxb + (uint32_t)(ks + 1) * (16 * WPITCH));
            MMA6(fah[s], fal[s], fbh[s], fbl[s]);
        }

        // ===== wait: peers' h pushes for buf cur are now visible =====
        CLUSTER_WAIT();

        // ===== phase 2: h-part (16 ks), register double-buffered =====
        LOADKS(0, ahb, 8192u, whb);
        #pragma unroll
        for (int ks = 0; ks < 16; ++ks) {
            const int s = ks & 1, n = s ^ 1;
            if (ks + 1 < 16)
                LOADKS(n, ahb + (uint32_t)(ks + 1) * 512, 8192u,
                       whb + (uint32_t)(ks + 1) * (16 * WPITCH));
            MMA6(fah[s], fal[s], fbh[s], fbl[s]);
        }

        // ---- scatter D to scratch [b][128] ----
        {
            const int r  = lane >> 2;
            const int c0 = 2 * (lane & 3);
            #pragma unroll
            for (int j = 0; j < 2; ++j) {
                const int col = 16 * warp + 8 * j + c0;
                float2* s0 = reinterpret_cast<float2*>(Scr + r * 128 + col);
                float2* s1 = reinterpret_cast<float2*>(Scr + (r + 8) * 128 + col);
                *s0 = make_float2(j ? d10 : d00, j ? d11 : d01);
                *s1 = make_float2(j ? d12 : d02, j ? d13 : d03);
            }
        }
        __syncthreads();

        // ---- stage x_{t+1} into buf nxt; prefetch x_{t+2} ----
        if (t + 1 < S_DIM) {
            const uint32_t xo = OFF_AX + (uint32_t)nxt * AXBUF;
            float vv[4] = {xv.x, xv.y, xv.z, xv.w};
            #pragma unroll
            for (int j = 0; j < 4; ++j) {
                uint16_t hi, lo;
                bfsplit(vv[j], hi, lo);
                uint32_t o = (uint32_t)(4 * kg + j) * 32 + (uint32_t)bx * 2;
                *reinterpret_cast<uint16_t*>(smem + xo + o)        = hi;
                *reinterpret_cast<uint16_t*>(smem + xo + 2048 + o) = lo;
            }
            if (t + 2 < S_DIM)
                xv = *reinterpret_cast<const float4*>(xsrc + (size_t)(t + 2) * I_DIM);
        }

        // ---- gates for (hd=lane, batches eb, eb+1) ----
        uint16_t h0hi, h0lo, h1hi, h1lo;
        {
            float4 q = *reinterpret_cast<const float4*>(Scr + eb * 128 + 4 * lane);
            float it = sigf(q.x), ft = sigf(q.y), gt = tanh_(q.z), ot = sigf(q.w);
            cs0 = fmaf(ft, cs0, it * gt);
            h0  = ot * tanh_(cs0);
            bfsplit(h0, h0hi, h0lo);
        }
        {
            float4 q = *reinterpret_cast<const float4*>(Scr + (eb + 1) * 128 + 4 * lane);
            float it = sigf(q.x), ft = sigf(q.y), gt = tanh_(q.z), ot = sigf(q.w);
            cs1 = fmaf(ft, cs1, it * gt);
            h1  = ot * tanh_(cs1);
            bfsplit(h1, h1hi, h1lo);
        }

        // hidden_seq[t][gb+eb..][ghd]
        float* op = out + (size_t)t * (B_DIM * H_DIM) + (size_t)(gb + eb) * H_DIM + ghd;
        op[0]     = h0;
        op[H_DIM] = h1;

        const uint32_t hiw = (uint32_t)h0hi | ((uint32_t)h1hi << 16);
        const uint32_t low = (uint32_t)h0lo | ((uint32_t)h1lo << 16);
        const uint32_t bo  = (uint32_t)nxt * AHBUF;

        // own panel slice (local) + staging for compact remote pushes
        *reinterpret_cast<uint32_t*>(smem + OFF_AH + bo + (uint32_t)(ghd * 32 + eb * 2))        = hiw;
        *reinterpret_cast<uint32_t*>(smem + OFF_AH + bo + 8192 + (uint32_t)(ghd * 32 + eb * 2)) = low;
        *reinterpret_cast<uint32_t*>(smem + OFF_HSTG + (uint32_t)(lane * 64 + eb * 2))          = hiw;
        *reinterpret_cast<uint32_t*>(smem + OFF_HSTG + (uint32_t)(lane * 64 + 32 + eb * 2))     = low;

        __syncthreads();   // Hstg + own slice + x staging complete

        // ---- compact push: 128 threads x 7 peers x 16B ----
        if (t + 1 < S_DIM) {
            if (tid < 128) {
                uint4 v = *reinterpret_cast<const uint4*>(smem + OFF_HSTG + psrc);
                #pragma unroll
                for (int p = 0; p < CLUSTER; ++p)
                    if ((uint32_t)p != rank)
                        stc128(mbAH[p] + bo + pdoff, v);
            }
            CLUSTER_ARRIVE();   // release: remote pushes ordered before peers' wait
        }
    }

    // ---- final h_t, c_t ----
    float* out_h = out + (size_t)S_DIM * B_DIM * H_DIM;
    float* out_c = out_h + (size_t)B_DIM * H_DIM;
    const size_t fb = (size_t)(gb + eb) * H_DIM + ghd;
    out_h[fb]         = h0;
    out_h[fb + H_DIM] = h1;
    out_c[fb]         = cs0;
    out_c[fb + H_DIM] = cs1;
}

extern "C" void kernel_launch(void* const* d_in, const int* in_sizes, int n_in,
                              void* d_out, int out_size) {
    const float* x   = (const float*)d_in[0];
    const float* w_i = (const float*)d_in[1];
    const float* u_i = (const float*)d_in[2];
    const float* b_i = (const float*)d_in[3];
    const float* w_f = (const float*)d_in[4];
    const float* u_f = (const float*)d_in[5];
    const float* b_f = (const float*)d_in[6];
    const float* w_c = (const float*)d_in[7];
    const float* u_c = (const float*)d_in[8];
    const float* b_c = (const float*)d_in[9];
    const float* w_o = (const float*)d_in[10];
    const float* u_o = (const float*)d_in[11];
    const float* b_o = (const float*)d_in[12];
    float* out = (float*)d_out;

    cudaFuncSetAttribute(lstm_hmma, cudaFuncAttributeMaxDynamicSharedMemorySize, SMEM_BYTES);

    dim3 grid((B_DIM / GBATCH) * CLUSTER);  // 16 clusters * 8 CTAs = 128
    lstm_hmma<<<grid, NTHREADS, SMEM_BYTES>>>(
        x, w_i, u_i, b_i, w_f, u_f, b_f, w_c, u_c, b_c, w_o, u_o, b_o, out);
}

// round 10
// speedup vs baseline: 2.9209x; 1.1802x over previous
#include <cuda_runtime.h>
#include <cuda_bf16.h>
#include <cstdint>

// Problem dims
#define B_DIM 256
#define S_DIM 512
#define I_DIM 64
#define H_DIM 256

#define CLUSTER 8
#define GBATCH 16
#define HSLICE 32
#define NTHREADS 256      // 8 warps

// Weights: [2 half][320 k][128 n] bf16, pitch 272B (conflict-free LDSM)
#define WPITCH 272
#define OFF_W   0
#define WHALF   (320 * WPITCH)            // 87040
// A x-panel: [2 buf][2 half][64 k][16 b] bf16
#define OFF_AX  (2 * WHALF)               // 174080
#define AXBUF   4096
// A h-panel: [2 buf][2 half][256 k][16 b] bf16
#define OFF_AH  (OFF_AX + 2 * AXBUF)      // 182272
#define AHBUF   16384
// scratch: [16 b][128 col] fp32
#define OFF_SCR (OFF_AH + 2 * AHBUF)      // 215040
// h staging for compact pushes: [32 hd][2 half][16 b] bf16 = 2KB
#define OFF_HSTG (OFF_SCR + 8192)         // 223232
#define SMEM_BYTES (OFF_HSTG + 2048)      // 225280

__device__ __forceinline__ float sigf(float x) {
    return __fdividef(1.0f, 1.0f + __expf(-x));
}
__device__ __forceinline__ float tanh_(float x) {
    return __fdividef(2.0f, 1.0f + __expf(-2.0f * x)) - 1.0f;
}

__device__ __forceinline__ uint32_t smem_u32(const void* p) {
    uint32_t a;
    asm("{ .reg .u64 t; cvta.to.shared.u64 t, %1; cvt.u32.u64 %0, t; }" : "=r"(a) : "l"(p));
    return a;
}
__device__ __forceinline__ uint32_t mapa_u32(uint32_t addr, uint32_t rank) {
    uint32_t r;
    asm("mapa.shared::cluster.u32 %0, %1, %2;" : "=r"(r) : "r"(addr), "r"(rank));
    return r;
}
__device__ __forceinline__ void stc128(uint32_t addr, uint4 v) {
    asm volatile("st.shared::cluster.v4.b32 [%0], {%1,%2,%3,%4};"
                 :: "r"(addr), "r"(v.x), "r"(v.y), "r"(v.z), "r"(v.w) : "memory");
}
#define CLUSTER_ARRIVE() asm volatile("barrier.cluster.arrive.aligned;" ::: "memory")
#define CLUSTER_WAIT()   asm volatile("barrier.cluster.wait.aligned;" ::: "memory")

#define LDSM4T(r0, r1, r2, r3, addr) \
    asm volatile("ldmatrix.sync.aligned.m8n8.x4.trans.shared.b16 {%0,%1,%2,%3}, [%4];" \
                 : "=r"(r0), "=r"(r1), "=r"(r2), "=r"(r3) : "r"(addr))

#define MMA(d0, d1, d2, d3, a0, a1, a2, a3, b0, b1) \
    asm volatile("mma.sync.aligned.m16n8k16.row.col.f32.bf16.bf16.f32 " \
                 "{%0,%1,%2,%3}, {%4,%5,%6,%7}, {%8,%9}, {%0,%1,%2,%3};" \
                 : "+f"(d0), "+f"(d1), "+f"(d2), "+f"(d3) \
                 : "r"(a0), "r"(a1), "r"(a2), "r"(a3), "r"(b0), "r"(b1))

__device__ __forceinline__ void bfsplit(float v, uint16_t& hi, uint16_t& lo) {
    __nv_bfloat16 h = __float2bfloat16(v);
    float r = v - __bfloat162float(h);
    __nv_bfloat16 l = __float2bfloat16(r);
    hi = *reinterpret_cast<uint16_t*>(&h);
    lo = *reinterpret_cast<uint16_t*>(&l);
}

// 6 MMAs (3-term bf16 split, 2 n-tiles); B fragments from registers
#define MMA6R(AH, AL, BH, BL) do { \
    MMA(d00, d01, d02, d03, (AH)[0], (AH)[1], (AH)[2], (AH)[3], (BH)[0], (BH)[1]); \
    MMA(d00, d01, d02, d03, (AH)[0], (AH)[1], (AH)[2], (AH)[3], (BL)[0], (BL)[1]); \
    MMA(d00, d01, d02, d03, (AL)[0], (AL)[1], (AL)[2], (AL)[3], (BH)[0], (BH)[1]); \
    MMA(d10, d11, d12, d13, (AH)[0], (AH)[1], (AH)[2], (AH)[3], (BH)[2], (BH)[3]); \
    MMA(d10, d11, d12, d13, (AH)[0], (AH)[1], (AH)[2], (AH)[3], (BL)[2], (BL)[3]); \
    MMA(d10, d11, d12, d13, (AL)[0], (AL)[1], (AL)[2], (AL)[3], (BH)[2], (BH)[3]); \
} while (0)

// A-only k-step load (hi + lo halves); ALOFF = 2048 (x panel) or 8192 (h panel)
#define LOADA(S, AADDR, ALOFF) do { \
    LDSM4T(fah[S][0], fah[S][1], fah[S][2], fah[S][3], (AADDR)); \
    LDSM4T(fal[S][0], fal[S][1], fal[S][2], fal[S][3], (AADDR) + (ALOFF)); \
} while (0)

__global__ void __cluster_dims__(CLUSTER, 1, 1) __launch_bounds__(NTHREADS, 1)
lstm_hmma(const float* __restrict__ x,
          const float* __restrict__ w_i, const float* __restrict__ u_i, const float* __restrict__ b_i,
          const float* __restrict__ w_f, const float* __restrict__ u_f, const float* __restrict__ b_f,
          const float* __restrict__ w_c, const float* __restrict__ u_c, const float* __restrict__ b_c,
          const float* __restrict__ w_o, const float* __restrict__ u_o, const float* __restrict__ b_o,
          float* __restrict__ out)
{
    extern __shared__ char smem[];
    const uint32_t sb = smem_u32(smem);
    const int tid  = threadIdx.x;
    const int lane = tid & 31;
    const int warp = tid >> 5;

    uint32_t rank;
    asm("mov.u32 %0, %%cluster_ctarank;" : "=r"(rank));
    const int gb   = (blockIdx.x / CLUSTER) * GBATCH;
    const int colh = (int)rank * HSLICE;

    // ---- stage weights to smem (once): W[half][k][n], n = 4*hd + g, bf16 hi/lo ----
    #pragma unroll
    for (int g = 0; g < 4; ++g) {
        const float* Wsrc = (g == 0) ? w_i : (g == 1) ? w_f : (g == 2) ? w_c : w_o;
        const float* Usrc = (g == 0) ? u_i : (g == 1) ? u_f : (g == 2) ? u_c : u_o;
        for (int k = warp; k < 320; k += 8) {
            const float* src = (k < I_DIM) ? (Wsrc + (size_t)k * H_DIM)
                                           : (Usrc + (size_t)(k - I_DIM) * H_DIM);
            float v = src[colh + lane];
            uint16_t hi, lo;
            bfsplit(v, hi, lo);
            uint32_t o = (uint32_t)k * WPITCH + (uint32_t)(4 * lane + g) * 2;
            *reinterpret_cast<uint16_t*>(smem + OFF_W + o)         = hi;
            *reinterpret_cast<uint16_t*>(smem + OFF_W + WHALF + o) = lo;
        }
    }
    // zero h panel buffer 0 (both halves)
    for (int i = tid; i < AHBUF / 4; i += NTHREADS)
        reinterpret_cast<uint32_t*>(smem + OFF_AH)[i] = 0;

    // ---- lane offsets for ldmatrix.x4.trans ----
    const int lg = lane >> 3, lr = lane & 7;
    const uint32_t aoff = (uint32_t)((((lg & 2) ? 8 : 0) + lr) * 32 + ((lg & 1) ? 16 : 0));
    const uint32_t boff = (uint32_t)((((lg & 1) ? 8 : 0) + lr) * WPITCH
                                     + (16 * warp + ((lg & 2) ? 8 : 0)) * 2);

    // ---- bias-initialized accumulator constants ----
    float biasA[2], biasB[2];
    #pragma unroll
    for (int j = 0; j < 2; ++j) {
        int c0 = 16 * warp + 8 * j + 2 * (lane & 3);
        int hd0 = c0 >> 2, g0 = c0 & 3;
        const float* p0 = (g0 == 0) ? b_i : (g0 == 2) ? b_c : (g0 == 1) ? b_f : b_o;
        const float* p1 = (g0 + 1 == 1) ? b_f : (g0 + 1 == 3) ? b_o : (g0 + 1 == 2) ? b_c : b_i;
        biasA[j] = p0[colh + hd0];
        biasB[j] = p1[colh + hd0];
    }

    // ---- epilogue constants: thread owns hd=lane, batches eb, eb+1 ----
    const int eb  = 2 * warp;
    const int ghd = colh + lane;

    // ---- pusher constants (tid < 128): 16-B chunk (hd, half, bgroup) ----
    const int phd   = tid & 31;
    const int phalf = (tid >> 5) & 1;
    const int pbg   = (tid >> 6) & 1;
    const uint32_t psrc  = (uint32_t)(phd * 64 + phalf * 32 + pbg * 16);
    const uint32_t pdoff = (uint32_t)(phalf * 8192 + (colh + phd) * 32 + pbg * 16);
    uint32_t mbAH[CLUSTER];
    #pragma unroll
    for (int p = 0; p < CLUSTER; ++p) mbAH[p] = mapa_u32(sb + OFF_AH, (uint32_t)p);

    // ---- x staging: thread (bx, kg) handles x[gb+bx][t][4kg..4kg+3] ----
    const int bx = tid & 15;
    const int kg = tid >> 4;
    const float* xsrc = x + (size_t)(gb + bx) * S_DIM * I_DIM + 4 * kg;

    {
        float4 v = *reinterpret_cast<const float4*>(xsrc);
        float vv[4] = {v.x, v.y, v.z, v.w};
        #pragma unroll
        for (int j = 0; j < 4; ++j) {
            uint16_t hi, lo;
            bfsplit(vv[j], hi, lo);
            uint32_t o = (uint32_t)(4 * kg + j) * 32 + (uint32_t)bx * 2;
            *reinterpret_cast<uint16_t*>(smem + OFF_AX + o)        = hi;
            *reinterpret_cast<uint16_t*>(smem + OFF_AX + 2048 + o) = lo;
        }
    }
    float4 xv = *reinterpret_cast<const float4*>(xsrc + I_DIM);  // x_1 prefetch

    __syncthreads();   // weights staged — safe to hoist B fragments

    // ---- hoist ALL B (weight) fragments into registers: 20 ks x 4 x 2 halves ----
    uint32_t wbh[20][4], wbl[20][4];
    {
        const uint32_t wb = sb + OFF_W + boff;
        #pragma unroll
        for (int ks = 0; ks < 20; ++ks) {
            LDSM4T(wbh[ks][0], wbh[ks][1], wbh[ks][2], wbh[ks][3],
                   wb + (uint32_t)ks * (16 * WPITCH));
            LDSM4T(wbl[ks][0], wbl[ks][1], wbl[ks][2], wbl[ks][3],
                   wb + (uint32_t)ks * (16 * WPITCH) + WHALF);
        }
    }

    float* Scr = reinterpret_cast<float*>(smem + OFF_SCR);
    float cs0 = 0.f, cs1 = 0.f, h0 = 0.f, h1 = 0.f;

    CLUSTER_ARRIVE();   // primes iteration-0 wait (h buffer 0 locally zeroed)

    for (int t = 0; t < S_DIM; ++t) {
        const int cur = t & 1;
        const int nxt = cur ^ 1;

        float d00 = biasA[0], d01 = biasB[0], d02 = biasA[0], d03 = biasB[0];
        float d10 = biasA[1], d11 = biasB[1], d12 = biasA[1], d13 = biasB[1];

        const uint32_t axb = sb + OFF_AX + (uint32_t)cur * AXBUF + aoff;
        const uint32_t ahb = sb + OFF_AH + (uint32_t)cur * AHBUF + aoff;

        uint32_t fah[2][4], fal[2][4];

        // ===== phase 1: x-part (4 ks) — independent of peers' h, overlaps barrier =====
        LOADA(0, axb, 2048u);
        #pragma unroll
        for (int ks = 0; ks < 4; ++ks) {
            const int s = ks & 1, n = s ^ 1;
            if (ks + 1 < 4)
                LOADA(n, axb + (uint32_t)(ks + 1) * 512, 2048u);
            MMA6R(fah[s], fal[s], wbh[ks], wbl[ks]);
        }

        // ===== wait: peers' h pushes for buf cur are now visible =====
        CLUSTER_WAIT();

        // ===== phase 2: h-part (16 ks), register double-buffered A =====
        LOADA(0, ahb, 8192u);
        #pragma unroll
        for (int ks = 0; ks < 16; ++ks) {
            const int s = ks & 1, n = s ^ 1;
            if (ks + 1 < 16)
                LOADA(n, ahb + (uint32_t)(ks + 1) * 512, 8192u);
            MMA6R(fah[s], fal[s], wbh[4 + ks], wbl[4 + ks]);
        }

        // ---- scatter D to scratch [b][128] ----
        {
            const int r  = lane >> 2;
            const int c0 = 2 * (lane & 3);
            #pragma unroll
            for (int j = 0; j < 2; ++j) {
                const int col = 16 * warp + 8 * j + c0;
                float2* s0 = reinterpret_cast<float2*>(Scr + r * 128 + col);
                float2* s1 = reinterpret_cast<float2*>(Scr + (r + 8) * 128 + col);
                *s0 = make_float2(j ? d10 : d00, j ? d11 : d01);
                *s1 = make_float2(j ? d12 : d02, j ? d13 : d03);
            }
        }
        __syncthreads();

        // ---- stage x_{t+1} into buf nxt; prefetch x_{t+2} ----
        if (t + 1 < S_DIM) {
            const uint32_t xo = OFF_AX + (uint32_t)nxt * AXBUF;
            float vv[4] = {xv.x, xv.y, xv.z, xv.w};
            #pragma unroll
            for (int j = 0; j < 4; ++j) {
                uint16_t hi, lo;
                bfsplit(vv[j], hi, lo);
                uint32_t o = (uint32_t)(4 * kg + j) * 32 + (uint32_t)bx * 2;
                *reinterpret_cast<uint16_t*>(smem + xo + o)        = hi;
                *reinterpret_cast<uint16_t*>(smem + xo + 2048 + o) = lo;
            }
            if (t + 2 < S_DIM)
                xv = *reinterpret_cast<const float4*>(xsrc + (size_t)(t + 2) * I_DIM);
        }

        // ---- gates for (hd=lane, batches eb, eb+1) ----
        uint16_t h0hi, h0lo, h1hi, h1lo;
        {
            float4 q = *reinterpret_cast<const float4*>(Scr + eb * 128 + 4 * lane);
            float it = sigf(q.x), ft = sigf(q.y), gt = tanh_(q.z), ot = sigf(q.w);
            cs0 = fmaf(ft, cs0, it * gt);
            h0  = ot * tanh_(cs0);
            bfsplit(h0, h0hi, h0lo);
        }
        {
            float4 q = *reinterpret_cast<const float4*>(Scr + (eb + 1) * 128 + 4 * lane);
            float it = sigf(q.x), ft = sigf(q.y), gt = tanh_(q.z), ot = sigf(q.w);
            cs1 = fmaf(ft, cs1, it * gt);
            h1  = ot * tanh_(cs1);
            bfsplit(h1, h1hi, h1lo);
        }

        // hidden_seq[t][gb+eb..][ghd]
        float* op = out + (size_t)t * (B_DIM * H_DIM) + (size_t)(gb + eb) * H_DIM + ghd;
        op[0]     = h0;
        op[H_DIM] = h1;

        const uint32_t hiw = (uint32_t)h0hi | ((uint32_t)h1hi << 16);
        const uint32_t low = (uint32_t)h0lo | ((uint32_t)h1lo << 16);
        const uint32_t bo  = (uint32_t)nxt * AHBUF;

        // own panel slice (local) + staging for compact remote pushes
        *reinterpret_cast<uint32_t*>(smem + OFF_AH + bo + (uint32_t)(ghd * 32 + eb * 2))        = hiw;
        *reinterpret_cast<uint32_t*>(smem + OFF_AH + bo + 8192 + (uint32_t)(ghd * 32 + eb * 2)) = low;
        *reinterpret_cast<uint32_t*>(smem + OFF_HSTG + (uint32_t)(lane * 64 + eb * 2))          = hiw;
        *reinterpret_cast<uint32_t*>(smem + OFF_HSTG + (uint32_t)(lane * 64 + 32 + eb * 2))     = low;

        __syncthreads();   // Hstg + own slice + x staging complete

        // ---- compact push: 128 threads x 7 peers x 16B ----
        if (t + 1 < S_DIM) {
            if (tid < 128) {
                uint4 v = *reinterpret_cast<const uint4*>(smem + OFF_HSTG + psrc);
                #pragma unroll
                for (int p = 0; p < CLUSTER; ++p)
                    if ((uint32_t)p != rank)
                        stc128(mbAH[p] + bo + pdoff, v);
            }
            CLUSTER_ARRIVE();   // release: remote pushes ordered before peers' wait
        }
    }

    // ---- final h_t, c_t ----
    float* out_h = out + (size_t)S_DIM * B_DIM * H_DIM;
    float* out_c = out_h + (size_t)B_DIM * H_DIM;
    const size_t fb = (size_t)(gb + eb) * H_DIM + ghd;
    out_h[fb]         = h0;
    out_h[fb + H_DIM] = h1;
    out_c[fb]         = cs0;
    out_c[fb + H_DIM] = cs1;
}

extern "C" void kernel_launch(void* const* d_in, const int* in_sizes, int n_in,
                              void* d_out, int out_size) {
    const float* x   = (const float*)d_in[0];
    const float* w_i = (const float*)d_in[1];
    const float* u_i = (const float*)d_in[2];
    const float* b_i = (const float*)d_in[3];
    const float* w_f = (const float*)d_in[4];
    const float* u_f = (const float*)d_in[5];
    const float* b_f = (const float*)d_in[6];
    const float* w_c = (const float*)d_in[7];
    const float* u_c = (const float*)d_in[8];
    const float* b_c = (const float*)d_in[9];
    const float* w_o = (const float*)d_in[10];
    const float* u_o = (const float*)d_in[11];
    const float* b_o = (const float*)d_in[12];
    float* out = (float*)d_out;

    cudaFuncSetAttribute(lstm_hmma, cudaFuncAttributeMaxDynamicSharedMemorySize, SMEM_BYTES);

    dim3 grid((B_DIM / GBATCH) * CLUSTER);  // 16 clusters * 8 CTAs = 128
    lstm_hmma<<<grid, NTHREADS, SMEM_BYTES>>>(
        x, w_i, u_i, b_i, w_f, u_f, b_f, w_c, u_c, b_c, w_o, u_o, b_o, out);
}

// round 11
// speedup vs baseline: 3.1234x; 1.0693x over previous
#include <cuda_runtime.h>
#include <cuda_bf16.h>
#include <cstdint>

// Problem dims
#define B_DIM 256
#define S_DIM 512
#define I_DIM 64
#define H_DIM 256

#define CLUSTER 8
#define GBATCH 16
#define HSLICE 32
#define NTHREADS 256      // 8 warps

// Weights: [2 half][320 k][128 n] bf16, pitch 272B (conflict-free LDSM)
#define WPITCH 272
#define OFF_W   0
#define WHALF   (320 * WPITCH)            // 87040
// A x-panel: [2 buf][2 half][64 k][16 b] bf16
#define OFF_AX  (2 * WHALF)               // 174080
#define AXBUF   4096
// A h-panel: [2 buf][2 half][256 k][16 b] bf16
#define OFF_AH  (OFF_AX + 2 * AXBUF)      // 182272
#define AHBUF   16384
// h staging for compact pushes: [32 hd][2 half][16 b] bf16 = 2KB
#define OFF_HSTG (OFF_AH + 2 * AHBUF)     // 215040
#define SMEM_BYTES (OFF_HSTG + 2048)      // 217088

__device__ __forceinline__ float sigf(float x) {
    return __fdividef(1.0f, 1.0f + __expf(-x));
}
__device__ __forceinline__ float tanh_(float x) {
    return __fdividef(2.0f, 1.0f + __expf(-2.0f * x)) - 1.0f;
}

__device__ __forceinline__ uint32_t smem_u32(const void* p) {
    uint32_t a;
    asm("{ .reg .u64 t; cvta.to.shared.u64 t, %1; cvt.u32.u64 %0, t; }" : "=r"(a) : "l"(p));
    return a;
}
__device__ __forceinline__ uint32_t mapa_u32(uint32_t addr, uint32_t rank) {
    uint32_t r;
    asm("mapa.shared::cluster.u32 %0, %1, %2;" : "=r"(r) : "r"(addr), "r"(rank));
    return r;
}
__device__ __forceinline__ void stc128(uint32_t addr, uint4 v) {
    asm volatile("st.shared::cluster.v4.b32 [%0], {%1,%2,%3,%4};"
                 :: "r"(addr), "r"(v.x), "r"(v.y), "r"(v.z), "r"(v.w) : "memory");
}
#define CLUSTER_ARRIVE() asm volatile("barrier.cluster.arrive.aligned;" ::: "memory")
#define CLUSTER_WAIT()   asm volatile("barrier.cluster.wait.aligned;" ::: "memory")

#define LDSM4T(r0, r1, r2, r3, addr) \
    asm volatile("ldmatrix.sync.aligned.m8n8.x4.trans.shared.b16 {%0,%1,%2,%3}, [%4];" \
                 : "=r"(r0), "=r"(r1), "=r"(r2), "=r"(r3) : "r"(addr))

#define MMA(d0, d1, d2, d3, a0, a1, a2, a3, b0, b1) \
    asm volatile("mma.sync.aligned.m16n8k16.row.col.f32.bf16.bf16.f32 " \
                 "{%0,%1,%2,%3}, {%4,%5,%6,%7}, {%8,%9}, {%0,%1,%2,%3};" \
                 : "+f"(d0), "+f"(d1), "+f"(d2), "+f"(d3) \
                 : "r"(a0), "r"(a1), "r"(a2), "r"(a3), "r"(b0), "r"(b1))

__device__ __forceinline__ void bfsplit(float v, uint16_t& hi, uint16_t& lo) {
    __nv_bfloat16 h = __float2bfloat16(v);
    float r = v - __bfloat162float(h);
    __nv_bfloat16 l = __float2bfloat16(r);
    hi = *reinterpret_cast<uint16_t*>(&h);
    lo = *reinterpret_cast<uint16_t*>(&l);
}

// 6 MMAs per k-step, 3 INDEPENDENT accumulator chains (hi*hi / hi*lo / lo*hi)
// x 2 n-tiles — all 6 mutually independent (chain length 20 instead of 60).
#define MMA6S(AH, AL, BH, BL) do { \
    MMA(aA[0][0], aA[0][1], aA[0][2], aA[0][3], (AH)[0], (AH)[1], (AH)[2], (AH)[3], (BH)[0], (BH)[1]); \
    MMA(aB[0][0], aB[0][1], aB[0][2], aB[0][3], (AH)[0], (AH)[1], (AH)[2], (AH)[3], (BL)[0], (BL)[1]); \
    MMA(aC[0][0], aC[0][1], aC[0][2], aC[0][3], (AL)[0], (AL)[1], (AL)[2], (AL)[3], (BH)[0], (BH)[1]); \
    MMA(aA[1][0], aA[1][1], aA[1][2], aA[1][3], (AH)[0], (AH)[1], (AH)[2], (AH)[3], (BH)[2], (BH)[3]); \
    MMA(aB[1][0], aB[1][1], aB[1][2], aB[1][3], (AH)[0], (AH)[1], (AH)[2], (AH)[3], (BL)[2], (BL)[3]); \
    MMA(aC[1][0], aC[1][1], aC[1][2], aC[1][3], (AL)[0], (AL)[1], (AL)[2], (AL)[3], (BH)[2], (BH)[3]); \
} while (0)

// A-only k-step load (hi + lo halves); ALOFF = 2048 (x panel) or 8192 (h panel)
#define LOADA(S, AADDR, ALOFF) do { \
    LDSM4T(fah[S][0], fah[S][1], fah[S][2], fah[S][3], (AADDR)); \
    LDSM4T(fal[S][0], fal[S][1], fal[S][2], fal[S][3], (AADDR) + (ALOFF)); \
} while (0)

__global__ void __cluster_dims__(CLUSTER, 1, 1) __launch_bounds__(NTHREADS, 1)
lstm_hmma(const float* __restrict__ x,
          const float* __restrict__ w_i, const float* __restrict__ u_i, const float* __restrict__ b_i,
          const float* __restrict__ w_f, const float* __restrict__ u_f, const float* __restrict__ b_f,
          const float* __restrict__ w_c, const float* __restrict__ u_c, const float* __restrict__ b_c,
          const float* __restrict__ w_o, const float* __restrict__ u_o, const float* __restrict__ b_o,
          float* __restrict__ out)
{
    extern __shared__ char smem[];
    const uint32_t sb = smem_u32(smem);
    const int tid  = threadIdx.x;
    const int lane = tid & 31;
    const int warp = tid >> 5;

    uint32_t rank;
    asm("mov.u32 %0, %%cluster_ctarank;" : "=r"(rank));
    const int gb   = (blockIdx.x / CLUSTER) * GBATCH;
    const int colh = (int)rank * HSLICE;

    // ---- stage weights to smem (once): W[half][k][n], n = 4*hd + g, bf16 hi/lo ----
    #pragma unroll
    for (int g = 0; g < 4; ++g) {
        const float* Wsrc = (g == 0) ? w_i : (g == 1) ? w_f : (g == 2) ? w_c : w_o;
        const float* Usrc = (g == 0) ? u_i : (g == 1) ? u_f : (g == 2) ? u_c : u_o;
        for (int k = warp; k < 320; k += 8) {
            const float* src = (k < I_DIM) ? (Wsrc + (size_t)k * H_DIM)
                                           : (Usrc + (size_t)(k - I_DIM) * H_DIM);
            float v = src[colh + lane];
            uint16_t hi, lo;
            bfsplit(v, hi, lo);
            uint32_t o = (uint32_t)k * WPITCH + (uint32_t)(4 * lane + g) * 2;
            *reinterpret_cast<uint16_t*>(smem + OFF_W + o)         = hi;
            *reinterpret_cast<uint16_t*>(smem + OFF_W + WHALF + o) = lo;
        }
    }
    // zero h panel buffer 0 (both halves)
    for (int i = tid; i < AHBUF / 4; i += NTHREADS)
        reinterpret_cast<uint32_t*>(smem + OFF_AH)[i] = 0;

    // ---- lane offsets for ldmatrix.x4.trans ----
    const int lg = lane >> 3, lr = lane & 7;
    const uint32_t aoff = (uint32_t)((((lg & 2) ? 8 : 0) + lr) * 32 + ((lg & 1) ? 16 : 0));
    const uint32_t boff = (uint32_t)((((lg & 1) ? 8 : 0) + lr) * WPITCH
                                     + (16 * warp + ((lg & 2) ? 8 : 0)) * 2);

    // ---- bias constants (per n-tile col pair; go into chain A init only) ----
    float biasA[2], biasB[2];
    #pragma unroll
    for (int j = 0; j < 2; ++j) {
        int c0 = 16 * warp + 8 * j + 2 * (lane & 3);
        int hd0 = c0 >> 2, g0 = c0 & 3;
        const float* p0 = (g0 == 0) ? b_i : (g0 == 2) ? b_c : (g0 == 1) ? b_f : b_o;
        const float* p1 = (g0 + 1 == 1) ? b_f : (g0 + 1 == 3) ? b_o : (g0 + 1 == 2) ? b_c : b_i;
        biasA[j] = p0[colh + hd0];
        biasB[j] = p1[colh + hd0];
    }

    // ---- epilogue (fragment-layout) constants ----
    // xor-1 lane pairs share one hd; rows r / r+8 split across the pair.
    const int odd  = lane & 1;
    const int ebat = (lane >> 2) + (odd ? 8 : 0);            // owned batch (both j)
    const int hdj0 = 4 * warp + ((lane & 3) >> 1);           // hd for j=0; j=1 adds 2
    const int ghd0 = colh + hdj0;

    // ---- pusher constants (tid < 128): 16-B chunk (hd, half, bgroup) ----
    const int phd   = tid & 31;
    const int phalf = (tid >> 5) & 1;
    const int pbg   = (tid >> 6) & 1;
    const uint32_t psrc  = (uint32_t)(phd * 64 + phalf * 32 + pbg * 16);
    const uint32_t pdoff = (uint32_t)(phalf * 8192 + (colh + phd) * 32 + pbg * 16);
    uint32_t mbAH[CLUSTER];
    #pragma unroll
    for (int p = 0; p < CLUSTER; ++p) mbAH[p] = mapa_u32(sb + OFF_AH, (uint32_t)p);

    // ---- x staging: thread (bx, kg) handles x[gb+bx][t][4kg..4kg+3] ----
    const int bx = tid & 15;
    const int kg = tid >> 4;
    const float* xsrc = x + (size_t)(gb + bx) * S_DIM * I_DIM + 4 * kg;

    {
        float4 v = *reinterpret_cast<const float4*>(xsrc);
        float vv[4] = {v.x, v.y, v.z, v.w};
        #pragma unroll
        for (int j = 0; j < 4; ++j) {
            uint16_t hi, lo;
            bfsplit(vv[j], hi, lo);
            uint32_t o = (uint32_t)(4 * kg + j) * 32 + (uint32_t)bx * 2;
            *reinterpret_cast<uint16_t*>(smem + OFF_AX + o)        = hi;
            *reinterpret_cast<uint16_t*>(smem + OFF_AX + 2048 + o) = lo;
        }
    }
    float4 xv = *reinterpret_cast<const float4*>(xsrc + I_DIM);  // x_1 prefetch

    __syncthreads();   // weights staged — safe to hoist B fragments

    // ---- hoist ALL B (weight) fragments into registers: 20 ks x 4 x 2 halves ----
    uint32_t wbh[20][4], wbl[20][4];
    {
        const uint32_t wb = sb + OFF_W + boff;
        #pragma unroll
        for (int ks = 0; ks < 20; ++ks) {
            LDSM4T(wbh[ks][0], wbh[ks][1], wbh[ks][2], wbh[ks][3],
                   wb + (uint32_t)ks * (16 * WPITCH));
            LDSM4T(wbl[ks][0], wbl[ks][1], wbl[ks][2], wbl[ks][3],
                   wb + (uint32_t)ks * (16 * WPITCH) + WHALF);
        }
    }

    float cs[2] = {0.f, 0.f};
    float hv[2] = {0.f, 0.f};

    CLUSTER_ARRIVE();   // primes iteration-0 wait (h buffer 0 locally zeroed)

    for (int t = 0; t < S_DIM; ++t) {
        const int cur = t & 1;
        const int nxt = cur ^ 1;

        float aA[2][4], aB[2][4], aC[2][4];
        #pragma unroll
        for (int j = 0; j < 2; ++j) {
            aA[j][0] = biasA[j]; aA[j][1] = biasB[j];
            aA[j][2] = biasA[j]; aA[j][3] = biasB[j];
            aB[j][0] = 0.f; aB[j][1] = 0.f; aB[j][2] = 0.f; aB[j][3] = 0.f;
            aC[j][0] = 0.f; aC[j][1] = 0.f; aC[j][2] = 0.f; aC[j][3] = 0.f;
        }

        const uint32_t axb = sb + OFF_AX + (uint32_t)cur * AXBUF + aoff;
        const uint32_t ahb = sb + OFF_AH + (uint32_t)cur * AHBUF + aoff;

        uint32_t fah[2][4], fal[2][4];

        // ===== phase 1: x-part (4 ks) — independent of peers' h, overlaps barrier =====
        LOADA(0, axb, 2048u);
        #pragma unroll
        for (int ks = 0; ks < 4; ++ks) {
            const int s = ks & 1, n = s ^ 1;
            if (ks + 1 < 4)
                LOADA(n, axb + (uint32_t)(ks + 1) * 512, 2048u);
            MMA6S(fah[s], fal[s], wbh[ks], wbl[ks]);
        }

        // ===== wait: peers' h pushes for buf cur are now visible =====
        CLUSTER_WAIT();

        // ===== phase 2: h-part (16 ks), register double-buffered A =====
        LOADA(0, ahb, 8192u);
        #pragma unroll
        for (int ks = 0; ks < 16; ++ks) {
            const int s = ks & 1, n = s ^ 1;
            if (ks + 1 < 16)
                LOADA(n, ahb + (uint32_t)(ks + 1) * 512, 8192u);
            MMA6S(fah[s], fal[s], wbh[4 + ks], wbl[4 + ks]);
        }

        // ---- stage x_{t+1} into buf nxt; prefetch x_{t+2} ----
        if (t + 1 < S_DIM) {
            const uint32_t xo = OFF_AX + (uint32_t)nxt * AXBUF;
            float vv[4] = {xv.x, xv.y, xv.z, xv.w};
            #pragma unroll
            for (int j = 0; j < 4; ++j) {
                uint16_t hi, lo;
                bfsplit(vv[j], hi, lo);
                uint32_t o = (uint32_t)(4 * kg + j) * 32 + (uint32_t)bx * 2;
                *reinterpret_cast<uint16_t*>(smem + xo + o)        = hi;
                *reinterpret_cast<uint16_t*>(smem + xo + 2048 + o) = lo;
            }
            if (t + 2 < S_DIM)
                xv = *reinterpret_cast<const float4*>(xsrc + (size_t)(t + 2) * I_DIM);
        }

        // ---- fragment-layout epilogue: shfl-exchange gates, no smem round-trip ----
        const uint32_t bo = (uint32_t)nxt * AHBUF;
        #pragma unroll
        for (int j = 0; j < 2; ++j) {
            float e0 = aA[j][0] + aB[j][0] + aC[j][0];   // (row r,   col 4hd+{0|2})
            float e1 = aA[j][1] + aB[j][1] + aC[j][1];   // (row r,   col 4hd+{1|3})
            float e2 = aA[j][2] + aB[j][2] + aC[j][2];   // (row r+8, ...)
            float e3 = aA[j][3] + aB[j][3] + aC[j][3];

            // even lane holds (i,f), odd holds (g,o); exchange the other pair,
            // even computes row r, odd computes row r+8.
            float s1 = odd ? e0 : e2;
            float s2 = odd ? e1 : e3;
            float r1 = __shfl_xor_sync(0xffffffffu, s1, 1);
            float r2 = __shfl_xor_sync(0xffffffffu, s2, 1);
            float gi = odd ? r1 : e0;
            float gf = odd ? r2 : e1;
            float gg = odd ? e2 : r1;
            float go = odd ? e3 : r2;

            float it = sigf(gi), ft = sigf(gf), gt = tanh_(gg), ot = sigf(go);
            cs[j] = fmaf(ft, cs[j], it * gt);
            hv[j] = ot * tanh_(cs[j]);

            const int ghd = ghd0 + 2 * j;
            // hidden_seq[t][gb+ebat][ghd]
            out[(size_t)t * (B_DIM * H_DIM) + (size_t)(gb + ebat) * H_DIM + ghd] = hv[j];

            uint16_t hh, hl;
            bfsplit(hv[j], hh, hl);
            // own panel slice (buf nxt)
            *reinterpret_cast<uint16_t*>(smem + OFF_AH + bo + (uint32_t)(ghd * 32 + ebat * 2))        = hh;
            *reinterpret_cast<uint16_t*>(smem + OFF_AH + bo + 8192 + (uint32_t)(ghd * 32 + ebat * 2)) = hl;
            // push staging [hd][half][b]
            const int hdl = hdj0 + 2 * j;
            *reinterpret_cast<uint16_t*>(smem + OFF_HSTG + (uint32_t)(hdl * 64 + ebat * 2))      = hh;
            *reinterpret_cast<uint16_t*>(smem + OFF_HSTG + (uint32_t)(hdl * 64 + 32 + ebat * 2)) = hl;
        }

        __syncthreads();   // Hstg + own slice + x staging complete

        // ---- compact push: 128 threads x 7 peers x 16B ----
        if (t + 1 < S_DIM) {
            if (tid < 128) {
                uint4 v = *reinterpret_cast<const uint4*>(smem + OFF_HSTG + psrc);
                #pragma unroll
                for (int p = 0; p < CLUSTER; ++p)
                    if ((uint32_t)p != rank)
                        stc128(mbAH[p] + bo + pdoff, v);
            }
            CLUSTER_ARRIVE();   // release: remote pushes ordered before peers' wait
        }
    }

    // ---- final h_t, c_t ----
    float* out_h = out + (size_t)S_DIM * B_DIM * H_DIM;
    float* out_c = out_h + (size_t)B_DIM * H_DIM;
    #pragma unroll
    for (int j = 0; j < 2; ++j) {
        const size_t fb = (size_t)(gb + ebat) * H_DIM + (ghd0 + 2 * j);
        out_h[fb] = hv[j];
        out_c[fb] = cs[j];
    }
}

extern "C" void kernel_launch(void* const* d_in, const int* in_sizes, int n_in,
                              void* d_out, int out_size) {
    const float* x   = (const float*)d_in[0];
    const float* w_i = (const float*)d_in[1];
    const float* u_i = (const float*)d_in[2];
    const float* b_i = (const float*)d_in[3];
    const float* w_f = (const float*)d_in[4];
    const float* u_f = (const float*)d_in[5];
    const float* b_f = (const float*)d_in[6];
    const float* w_c = (const float*)d_in[7];
    const float* u_c = (const float*)d_in[8];
    const float* b_c = (const float*)d_in[9];
    const float* w_o = (const float*)d_in[10];
    const float* u_o = (const float*)d_in[11];
    const float* b_o = (const float*)d_in[12];
    float* out = (float*)d_out;

    cudaFuncSetAttribute(lstm_hmma, cudaFuncAttributeMaxDynamicSharedMemorySize, SMEM_BYTES);

    dim3 grid((B_DIM / GBATCH) * CLUSTER);  // 16 clusters * 8 CTAs = 128
    lstm_hmma<<<grid, NTHREADS, SMEM_BYTES>>>(
        x, w_i, u_i, b_i, w_f, u_f, b_f, w_c, u_c, b_c, w_o, u_o, b_o, out);
}